// round 14
// baseline (speedup 1.0000x reference)
#include <cuda_runtime.h>
#include <cuda_bf16.h>
#include <math.h>
#include <stdint.h>

#define TT 256
#define BB_ 256
#define DD 512
#define AA 32
#define LL 3
#define MM (TT*BB_)            // 65536 rows
#define TBD ((size_t)MM*DD)    // 33554432
#define BD (BB_*DD)            // 131072

// arch-specific feature gate: tcgen05 only exists in the sm_103a ("a") pass
#if defined(__CUDA_ARCH__) && (defined(__CUDA_ARCH_FEAT_SM103_ALL) || \
    (defined(__CUDA_ARCH_SPECIFIC__) && (__CUDA_ARCH_SPECIFIC__ == 1030)))
#define HAS_TCGEN05 1
#else
#define HAS_TCGEN05 0
#endif

// ---------------- scratch (device globals; no runtime allocation) -----------
__device__ float g_bufA[TT*BB_*DD];
__device__ float g_bufB[TT*BB_*DD];
__device__ float g_X[3ull*TT*BB_*DD];
__device__ float g_y[TT*BB_*DD];

// grid-barrier state for persistent GRU scan
__device__ unsigned g_bar_count = 0;
__device__ unsigned g_bar_gen   = 0;

// ---------------- generic helpers --------------------------------------------
__device__ __forceinline__ uint32_t f2tf32(float x) {
    uint32_t r;
    asm("cvt.rna.tf32.f32 %0, %1;" : "=r"(r) : "f"(x));
    return r;
}

__device__ __forceinline__ void cp_async16(void* smem_ptr, const void* gmem_ptr) {
    uint32_t s = (uint32_t)__cvta_generic_to_shared(smem_ptr);
    asm volatile("cp.async.cg.shared.global [%0], [%1], 16;" :: "r"(s), "l"(gmem_ptr));
}

__device__ __forceinline__ unsigned ld_acquire_u32(unsigned* p) {
    unsigned v;
    asm volatile("ld.acquire.gpu.u32 %0, [%1];" : "=r"(v) : "l"(p) : "memory");
    return v;
}

// release/acquire grid barrier; all NBLK blocks must be co-resident
__device__ __forceinline__ void grid_barrier(unsigned nblk) {
    __threadfence();
    __syncthreads();
    if (threadIdx.x == 0) {
        unsigned gen = *((volatile unsigned*)&g_bar_gen);   // read BEFORE arrive
        unsigned arrived = atomicAdd(&g_bar_count, 1u);
        if (arrived == nblk - 1) {
            g_bar_count = 0;
            __threadfence();
            atomicAdd(&g_bar_gen, 1u);
        } else {
            while (ld_acquire_u32(&g_bar_gen) == gen) { __nanosleep(64); }
        }
    }
    __syncthreads();
}

__device__ __forceinline__ uint32_t smem_to_u32(const void* smem_ptr) {
    uint32_t addr;
    asm("{ .reg .u64 tmp; cvta.to.shared.u64 tmp, %1; cvt.u32.u64 %0, tmp; }"
        : "=r"(addr) : "l"(smem_ptr));
    return addr;
}

#define MBAR_INIT(mbar, cnt) \
    asm volatile("mbarrier.init.shared.b64 [%0], %1;" \
        :: "r"((uint32_t)(mbar)), "r"((uint32_t)(cnt)) : "memory")

#define MBAR_WAIT_PARITY(mbar_addr, parity) do { \
    uint32_t _m = (uint32_t)(mbar_addr); \
    uint32_t _p = (uint32_t)(parity); \
    uint32_t _done; \
    asm volatile( \
        "{\n\t.reg .pred p;\n\t" \
        "mbarrier.try_wait.parity.acquire.cta.shared::cta.b64 p, [%1], %2;\n\t" \
        "selp.b32 %0, 1, 0, p;\n\t}" \
        : "=r"(_done) : "r"(_m), "r"(_p) : "memory"); \
    if (!_done) { \
        asm volatile( \
            "{\n\t.reg .pred P1;\n\t" \
            "WAIT_LOOP_%=:\n\t" \
            "mbarrier.try_wait.parity.acquire.cta.shared::cta.b64 P1, [%0], %1, 0x989680;\n\t" \
            "@P1 bra.uni WAIT_DONE_%=;\n\t" \
            "bra.uni WAIT_LOOP_%=;\n\t" \
            "WAIT_DONE_%=:\n\t}" \
            :: "r"(_m), "r"(_p) : "memory"); \
    } \
} while(0)

#if HAS_TCGEN05
// ---------------- tcgen05 helpers (sm_103a pass only) ------------------------
__device__ __forceinline__ uint32_t elect_one_pred() {
    uint32_t pred;
    asm volatile(
        "{\n\t.reg .pred p;\n\telect.sync _|p, 0xFFFFFFFF;\n\tselp.b32 %0, 1, 0, p;\n\t}"
        : "=r"(pred));
    return pred;
}

#define TCG_ALLOC(smem_result_addr, nCols) \
    asm volatile("tcgen05.alloc.cta_group::1.sync.aligned.shared::cta.b32 [%0], %1;" \
        :: "r"((uint32_t)(smem_result_addr)), "r"((uint32_t)(nCols)) : "memory")
#define TCG_DEALLOC(tmem_addr, nCols) \
    asm volatile("tcgen05.dealloc.cta_group::1.sync.aligned.b32 %0, %1;" \
        :: "r"(tmem_addr), "r"((uint32_t)(nCols)))
#define TCG_COMMIT(mbar) \
    asm volatile("tcgen05.commit.cta_group::1.mbarrier::arrive::one.shared::cluster.b64 [%0];" \
        :: "r"((uint32_t)(mbar)) : "memory")
#define TCG_FENCE_BEFORE() asm volatile("tcgen05.fence::before_thread_sync;" ::: "memory")
#define TCG_FENCE_AFTER()  asm volatile("tcgen05.fence::after_thread_sync;" ::: "memory")
#define FENCE_PROXY_ASYNC() asm volatile("fence.proxy.async.shared::cta;" ::: "memory")
#define TCG_WAIT_LD() asm volatile("tcgen05.wait::ld.sync.aligned;" ::: "memory")

#define TCG_LD_32X32B_X32(r, tmem_addr) \
    asm volatile( \
        "tcgen05.ld.sync.aligned.32x32b.x32.b32 " \
        "{%0, %1, %2, %3, %4, %5, %6, %7, " \
        " %8, %9, %10, %11, %12, %13, %14, %15, " \
        " %16, %17, %18, %19, %20, %21, %22, %23, " \
        " %24, %25, %26, %27, %28, %29, %30, %31}, [%32];" \
        : "=r"((r)[0]),  "=r"((r)[1]),  "=r"((r)[2]),  "=r"((r)[3]), \
          "=r"((r)[4]),  "=r"((r)[5]),  "=r"((r)[6]),  "=r"((r)[7]), \
          "=r"((r)[8]),  "=r"((r)[9]),  "=r"((r)[10]), "=r"((r)[11]), \
          "=r"((r)[12]), "=r"((r)[13]), "=r"((r)[14]), "=r"((r)[15]), \
          "=r"((r)[16]), "=r"((r)[17]), "=r"((r)[18]), "=r"((r)[19]), \
          "=r"((r)[20]), "=r"((r)[21]), "=r"((r)[22]), "=r"((r)[23]), \
          "=r"((r)[24]), "=r"((r)[25]), "=r"((r)[26]), "=r"((r)[27]), \
          "=r"((r)[28]), "=r"((r)[29]), "=r"((r)[30]), "=r"((r)[31]) \
        : "r"(tmem_addr))

__device__ __forceinline__ void tcg_mma_f16_ss(
    uint32_t d_tmem, uint64_t a_desc, uint64_t b_desc, uint32_t idesc, bool en)
{
    uint32_t e = en ? 1u : 0u;
    asm volatile(
        "{\n\t.reg .pred p;\n\tsetp.ne.u32 p, %4, 0;\n\t"
        "tcgen05.mma.cta_group::1.kind::f16 [%0], %1, %2, %3, {%5, %5, %5, %5}, p;\n\t}"
        :: "r"(d_tmem), "l"(a_desc), "l"(b_desc), "r"(idesc), "r"(e), "r"(0u)
        : "memory");
}
#endif  // HAS_TCGEN05

// SW128 K-major smem descriptor: layout=2, version=1(Blackwell), SBO=64, LBO=1
static constexpr uint64_t SMEM_DESC_BASE_SW128 =
    (uint64_t(2) << 61) | (uint64_t(1) << 46) | (uint64_t(64) << 32) | (uint64_t(1) << 16);
#define MAKE_DESC(addr) (SMEM_DESC_BASE_SW128 | ((uint64_t)((addr) >> 4) & 0x3FFF))
#define SWZ128(off) ((off) ^ (((off) >> 3) & 0x70))

// idesc kind::f16: dtype F32(1<<4), atype BF16(1<<7), btype BF16(1<<10),
// N=128 -> 16<<17, M=128 -> 8<<24   (formula validated by test_mma.cu)
static constexpr uint32_t IDESC_BF16_128x128 =
    (1u << 4) | (1u << 7) | (1u << 10) | (16u << 17) | (8u << 24);

// split fp32 -> (hi, lo) bf16 pairs packed as bf16x2 words (low 16 = even elem)
__device__ __forceinline__ uint32_t split_pack(float a, float b, uint32_t& lo) {
    __nv_bfloat16 ha = __float2bfloat16(a);
    __nv_bfloat16 hb = __float2bfloat16(b);
    __nv_bfloat16 la = __float2bfloat16(a - __bfloat162float(ha));
    __nv_bfloat16 lb = __float2bfloat16(b - __bfloat162float(hb));
    lo = (uint32_t)__bfloat16_as_ushort(la) | ((uint32_t)__bfloat16_as_ushort(lb) << 16);
    return (uint32_t)__bfloat16_as_ushort(ha) | ((uint32_t)__bfloat16_as_ushort(hb) << 16);
}

// ---------------- big GEMM 128x128 tile, dual path ----------------------------
// sm_103a pass: tcgen05 split-bf16 (D += Ahi*Bhi + Ahi*Blo + Alo*Bhi, fp32 acc)
// other passes: tf32 mma.sync 3-stage cp.async (known correct)
// smem (132096 B): [0]tmem ptr, [8]mbar0, [16]mbar1; tiles at 1024: 2 x 64KB
#define G5_BUF   65536
#define G5_ALO   16384
#define G5_BHI   32768
#define G5_BLO   49152
#define G5_SMEM  (1024 + 2*G5_BUF)     // 132096 bytes (>= tf32 path's 107KB)
#define AS_STRIDE 4608
#define BS_STRIDE 4352

__global__ __launch_bounds__(256, 1) void gemm_big(
    const float* __restrict__ A, const float* __restrict__ W,
    float* __restrict__ C, const float* __restrict__ bias,
    int M, int N, int K)
{
#if HAS_TCGEN05
    extern __shared__ char smem[];
    const uint32_t smem_base = smem_to_u32(smem);
    const int tid = threadIdx.x;
    const int wid = tid >> 5, lane = tid & 31;
    const int bx = blockIdx.x, by = blockIdx.y;

    if (wid == 0) {
        TCG_ALLOC(smem_base + 0, 128);
    }
    if (tid == 0) {
        MBAR_INIT(smem_base + 8, 1);
        MBAR_INIT(smem_base + 16, 1);
    }
    __syncthreads();
    uint32_t tmem_base;
    asm volatile("ld.shared.b32 %0, [%1];" : "=r"(tmem_base) : "r"(smem_base + 0));

    const float* Ab = A + (size_t)by * 128 * K;
    const float* Wb = W + (size_t)bx * 128;

    // loader coords
    const int arow = tid >> 1;            // 0..127
    const int akq  = (tid & 1) * 32;      // k sub-block 0 or 32
    const int bn   = tid & 127;           // 0..127 (B tile row = n)
    const int bkh  = (tid >> 7) * 32;     // k sub-block 0 or 32

    const int nchunks = K >> 6;           // K/64
    int phase[2] = {0, 0};

    for (int c = 0; c < nchunks; c++) {
        const int buf = c & 1;
        if (c >= 2) {
            MBAR_WAIT_PARITY(smem_base + 8 + buf * 8, phase[buf]);
            phase[buf] ^= 1;
        }
        char* tb = smem + 1024 + buf * G5_BUF;

        // ---- A chunk: 128 rows x 64 k (fp32 -> hi/lo bf16, SW128) ----
        const float* Ap = Ab + (size_t)arow * K + c * 64 + akq;
        #pragma unroll
        for (int i = 0; i < 8; i++) {
            float4 v = *(const float4*)(Ap + i * 4);
            uint32_t lo0, lo1;
            uint32_t hi0 = split_pack(v.x, v.y, lo0);
            uint32_t hi1 = split_pack(v.z, v.w, lo1);
            uint32_t b0 = SWZ128((uint32_t)(arow * 128 + (akq + i * 4) * 2));
            uint32_t b1 = SWZ128((uint32_t)(arow * 128 + (akq + i * 4 + 2) * 2));
            *(uint32_t*)(tb + b0)          = hi0;
            *(uint32_t*)(tb + b1)          = hi1;
            *(uint32_t*)(tb + G5_ALO + b0) = lo0;
            *(uint32_t*)(tb + G5_ALO + b1) = lo1;
        }

        // ---- B chunk: W[k][n] -> tile[n][k], 128 n-rows x 64 k ----
        const float* Wp = Wb + (size_t)(c * 64 + bkh) * N + bn;
        #pragma unroll
        for (int j = 0; j < 32; j += 2) {
            float v0 = Wp[(size_t)j * N];
            float v1 = Wp[(size_t)(j + 1) * N];
            uint32_t lo;
            uint32_t hi = split_pack(v0, v1, lo);
            uint32_t bo = SWZ128((uint32_t)(bn * 128 + (bkh + j) * 2));
            *(uint32_t*)(tb + G5_BHI + bo) = hi;
            *(uint32_t*)(tb + G5_BLO + bo) = lo;
        }

        FENCE_PROXY_ASYNC();
        __syncthreads();

        if (wid == 0 && elect_one_pred()) {
            uint32_t tbu = smem_base + 1024 + buf * G5_BUF;
            uint64_t ah = MAKE_DESC(tbu);
            uint64_t al = MAKE_DESC(tbu + G5_ALO);
            uint64_t bh = MAKE_DESC(tbu + G5_BHI);
            uint64_t bl = MAKE_DESC(tbu + G5_BLO);
            #pragma unroll
            for (int ks = 0; ks < 4; ks++) {      // K=16 bf16 per mma, +2 desc units/step
                uint64_t off = (uint64_t)(ks * 2);
                tcg_mma_f16_ss(tmem_base, ah + off, bh + off, IDESC_BF16_128x128,
                               !(c == 0 && ks == 0));
                tcg_mma_f16_ss(tmem_base, ah + off, bl + off, IDESC_BF16_128x128, true);
                tcg_mma_f16_ss(tmem_base, al + off, bh + off, IDESC_BF16_128x128, true);
            }
            TCG_COMMIT(smem_base + 8 + buf * 8);
        }
        // next chunk writes the other buffer; reuse gated by mbarrier wait above
    }

    // wait for the last two chunks' mma completion
    MBAR_WAIT_PARITY(smem_base + 8,  phase[0]);
    MBAR_WAIT_PARITY(smem_base + 16, phase[1]);
    TCG_FENCE_AFTER();
    __syncthreads();

    // ---- epilogue: TMEM -> smem (padded) -> coalesced gmem ----
    float* ds = (float*)(smem + 1024);    // 128 x 132 fp32 (tile bufs dead now)
    if (wid < 4) {
        int row = wid * 32 + lane;
        #pragma unroll
        for (int r = 0; r < 4; r++) {
            uint32_t regs[32];
            TCG_LD_32X32B_X32(regs, tmem_base + r * 32);
            TCG_WAIT_LD();
            #pragma unroll
            for (int q = 0; q < 32; q++)
                ds[row * 132 + r * 32 + q] = __uint_as_float(regs[q]);
        }
        TCG_FENCE_BEFORE();
    }
    __syncthreads();
    {
        int row = tid >> 1;
        int cb  = (tid & 1) * 64;
        float* crow = C + (size_t)(by * 128 + row) * N + bx * 128 + cb;
        #pragma unroll
        for (int i = 0; i < 16; i++) {
            float4 v = *(float4*)(ds + row * 132 + cb + i * 4);
            if (bias) {
                float4 b = *(const float4*)(bias + bx * 128 + cb + i * 4);
                v.x += b.x; v.y += b.y; v.z += b.z; v.w += b.w;
            }
            *(float4*)(crow + i * 4) = v;
        }
    }
    __syncthreads();
    if (wid == 0) TCG_DEALLOC(tmem_base, 128);

#else  // ---- fallback: tf32 mma.sync, 3-stage cp.async (known correct) ------
    extern __shared__ char smem_raw[];
    float* sm = (float*)smem_raw;
    float* AsBase = sm;                       // stage s at s*4608, [row*36 + k]
    float* BsBase = sm + 3 * AS_STRIDE;       // stage s at s*4352, [krow*136 + n]

    const int bx = blockIdx.x;
    const int by = blockIdx.y;
    const int tid = threadIdx.x;
    const int warp = tid >> 5, lane = tid & 31;
    const int wm = warp & 1, wn = warp >> 1;
    const int m_w = wm * 64, n_w = wn * 32;
    const int g  = lane >> 2;
    const int tg = lane & 3;

    const float* Ab = A + (size_t)by * 128 * K;
    const float* Wb = W + (size_t)bx * 128;

    const int a_row = tid >> 1;
    const int a_kq  = (tid & 1) * 16;
    const int b_kr  = tid >> 5;
    const int b_nq  = (tid & 31) * 4;

    float c[4][4][4];
    #pragma unroll
    for (int i = 0; i < 4; i++)
        #pragma unroll
        for (int j = 0; j < 4; j++)
            #pragma unroll
            for (int q = 0; q < 4; q++) c[i][j][q] = 0.f;

    auto issue_load = [&](int k0, int s) {
        float* As = AsBase + s * AS_STRIDE;
        float* Bs = BsBase + s * BS_STRIDE;
        #pragma unroll
        for (int i = 0; i < 4; i++) {
            cp_async16(&As[a_row * 36 + a_kq + i * 4],
                       Ab + (size_t)a_row * K + k0 + a_kq + i * 4);
        }
        #pragma unroll
        for (int i = 0; i < 4; i++) {
            int kr = b_kr + i * 8;
            cp_async16(&Bs[kr * 136 + b_nq],
                       Wb + (size_t)(k0 + kr) * N + b_nq);
        }
        asm volatile("cp.async.commit_group;");
    };

    issue_load(0, 0);
    if (K > 32) issue_load(32, 1);

    int s = 0;
    for (int k0 = 0; k0 < K; k0 += 32) {
        if (k0 + 64 < K) {
            int s2 = s + 2; if (s2 >= 3) s2 -= 3;
            issue_load(k0 + 64, s2);
            asm volatile("cp.async.wait_group 2;");
        } else if (k0 + 32 < K) {
            asm volatile("cp.async.wait_group 1;");
        } else {
            asm volatile("cp.async.wait_group 0;");
        }
        __syncthreads();

        const float* As = AsBase + s * AS_STRIDE;
        const float* Bs = BsBase + s * BS_STRIDE;

        #pragma unroll
        for (int kk = 0; kk < 4; kk++) {
            const int kb = kk * 8;
            uint32_t af[4][4];
            #pragma unroll
            for (int mi = 0; mi < 4; mi++) {
                int rb = m_w + mi * 16;
                af[mi][0] = f2tf32(As[(rb + g    ) * 36 + kb + tg    ]);
                af[mi][1] = f2tf32(As[(rb + g + 8) * 36 + kb + tg    ]);
                af[mi][2] = f2tf32(As[(rb + g    ) * 36 + kb + tg + 4]);
                af[mi][3] = f2tf32(As[(rb + g + 8) * 36 + kb + tg + 4]);
            }
            uint32_t bf[4][2];
            #pragma unroll
            for (int ni = 0; ni < 4; ni++) {
                int nb = n_w + ni * 8;
                bf[ni][0] = f2tf32(Bs[(kb + tg    ) * 136 + nb + g]);
                bf[ni][1] = f2tf32(Bs[(kb + tg + 4) * 136 + nb + g]);
            }
            #pragma unroll
            for (int mi = 0; mi < 4; mi++)
                #pragma unroll
                for (int ni = 0; ni < 4; ni++) {
                    asm volatile(
                        "mma.sync.aligned.m16n8k8.row.col.f32.tf32.tf32.f32 "
                        "{%0,%1,%2,%3}, {%4,%5,%6,%7}, {%8,%9}, {%0,%1,%2,%3};"
                        : "+f"(c[mi][ni][0]), "+f"(c[mi][ni][1]),
                          "+f"(c[mi][ni][2]), "+f"(c[mi][ni][3])
                        : "r"(af[mi][0]), "r"(af[mi][1]), "r"(af[mi][2]), "r"(af[mi][3]),
                          "r"(bf[ni][0]), "r"(bf[ni][1]));
                }
        }
        __syncthreads();
        s = s + 1; if (s >= 3) s -= 3;
    }

    #pragma unroll
    for (int mi = 0; mi < 4; mi++) {
        int r0 = by * 128 + m_w + mi * 16 + g;
        #pragma unroll
        for (int ni = 0; ni < 4; ni++) {
            int cc = bx * 128 + n_w + ni * 8 + tg * 2;
            float b0 = 0.f, b1 = 0.f;
            if (bias) { b0 = bias[cc]; b1 = bias[cc + 1]; }
            float2 v0 = make_float2(c[mi][ni][0] + b0, c[mi][ni][1] + b1);
            float2 v1 = make_float2(c[mi][ni][2] + b0, c[mi][ni][3] + b1);
            *(float2*)(C + (size_t)r0 * N + cc)       = v0;
            *(float2*)(C + (size_t)(r0 + 8) * N + cc) = v1;
        }
    }
#endif
}

// ---------------- tiny launch-index shifter (ncu -s 5 lands on gemm #3) ------
__global__ void warmup_kernel() { if (threadIdx.x == 0) g_bar_count = 0; }

// ---------------- row LayerNorm(+bias) + scale/shift + ReLU, in place --------
__global__ __launch_bounds__(128) void ln_bias_relu(
    float* __restrict__ X, const float* __restrict__ bias,
    const float* __restrict__ gamma, const float* __restrict__ beta)
{
    const int row = blockIdx.x;
    const int tid = threadIdx.x;
    float* xp = X + (size_t)row * DD + tid * 4;
    float4 v = *(float4*)xp;
    float4 bb = *(const float4*)(bias + tid * 4);
    v.x += bb.x; v.y += bb.y; v.z += bb.z; v.w += bb.w;

    float s  = v.x + v.y + v.z + v.w;
    float sq = v.x*v.x + v.y*v.y + v.z*v.z + v.w*v.w;
    #pragma unroll
    for (int o = 16; o > 0; o >>= 1) {
        s  += __shfl_down_sync(0xffffffffu, s,  o);
        sq += __shfl_down_sync(0xffffffffu, sq, o);
    }
    __shared__ float ws[4], wq[4];
    if ((tid & 31) == 0) { ws[tid >> 5] = s; wq[tid >> 5] = sq; }
    __syncthreads();
    float st = ws[0] + ws[1] + ws[2] + ws[3];
    float qt = wq[0] + wq[1] + wq[2] + wq[3];
    float mean = st * (1.f / DD);
    float var  = qt * (1.f / DD) - mean * mean;
    float inv  = rsqrtf(var + 1e-6f);

    float4 g = *(const float4*)(gamma + tid * 4);
    float4 b2 = *(const float4*)(beta + tid * 4);
    float4 o;
    o.x = fmaxf((v.x - mean) * inv * g.x + b2.x, 0.f);
    o.y = fmaxf((v.y - mean) * inv * g.y + b2.y, 0.f);
    o.z = fmaxf((v.z - mean) * inv * g.z + b2.z, 0.f);
    o.w = fmaxf((v.w - mean) * inv * g.w + b2.w, 0.f);
    *(float4*)xp = o;
}

// ---------------- persistent GRU scan (tf32 mma + grid barrier) --------------
#define GRU_NBLK 64
#define GRU_SMEM_WORDS (3*512*16 + 128*132)    // Ws + hs = 41472 words

__device__ __forceinline__ float sigmoidf_(float x) { return 1.f / (1.f + expf(-x)); }

__global__ __launch_bounds__(256, 1) void gru_scan(
    const float* __restrict__ hidden,
    const float* __restrict__ X,
    const int* __restrict__ dones,
    const float* __restrict__ Wh,
    const float* __restrict__ bhn,
    float* __restrict__ y)
{
    extern __shared__ uint32_t smem_u[];
    uint32_t* Ws = smem_u;
    uint32_t* hs = smem_u + 3*512*16;

    const int bi = blockIdx.x;
    const int nb = bi >> 5;
    const int nd = bi & 31;
    const int b0 = nb * 128;
    const int d0 = nd * 16;

    const int tid  = threadIdx.x;
    const int warp = tid >> 5, lane = tid & 31;
    const int wm = warp & 3, wn = warp >> 2;
    const int m_base = wm * 32;
    const int n8 = wn * 8;
    const int g  = lane >> 2;
    const int tg = lane & 3;

    #pragma unroll 4
    for (int i = 0; i < 24; i++) {
        int q = tid + i * 256;
        int gate = q >> 11;
        int rem  = q & 2047;
        int k    = rem >> 2;
        int dl4  = (rem & 3) * 4;
        float4 w = *(const float4*)(Wh + ((size_t)gate * 512 + k) * 512 + d0 + dl4);
        uint4 u = make_uint4(f2tf32(w.x), f2tf32(w.y), f2tf32(w.z), f2tf32(w.w));
        *(uint4*)(&Ws[((gate << 9) + k) * 16 + dl4]) = u;
    }

    const int dcol = d0 + n8 + tg * 2;
    const float bh0 = bhn[dcol], bh1 = bhn[dcol + 1];
    __syncthreads();

    for (int t = 0; t < TT; t++) {
        const float* hprev = (t == 0) ? hidden : (y + (size_t)(t - 1) * BD);
        const int* dn = dones + (size_t)t * BB_;

        float2 xr2[4], xz2[4], xn2[4], hp2[4];
        #pragma unroll
        for (int j = 0; j < 4; j++) {
            int bglob = b0 + m_base + j * 8 + g;
            int df = dn[bglob];
            size_t gi = (size_t)bglob * DD + dcol;
            hp2[j] = df ? make_float2(0.f, 0.f) : *(const float2*)(hprev + gi);
            size_t xi = (size_t)t * BD + gi;
            xr2[j] = *(const float2*)(X + xi);
            xz2[j] = *(const float2*)(X + TBD + xi);
            xn2[j] = *(const float2*)(X + 2 * TBD + xi);
        }

        float c[2][3][4];
        #pragma unroll
        for (int mi = 0; mi < 2; mi++)
            #pragma unroll
            for (int gt = 0; gt < 3; gt++)
                #pragma unroll
                for (int q = 0; q < 4; q++) c[mi][gt][q] = 0.f;

        for (int kc = 0; kc < 4; kc++) {
            const int kbase = kc * 128;
            #pragma unroll 4
            for (int i = 0; i < 16; i++) {
                int linear = tid + i * 256;
                int row = linear >> 5;
                int c4  = (linear & 31) * 4;
                int gb  = b0 + row;
                float4 v;
                if (dn[gb]) v = make_float4(0.f, 0.f, 0.f, 0.f);
                else v = *(const float4*)(hprev + (size_t)gb * DD + kbase + c4);
                uint4 u = make_uint4(f2tf32(v.x), f2tf32(v.y), f2tf32(v.z), f2tf32(v.w));
                *(uint4*)(&hs[row * 132 + c4]) = u;
            }
            __syncthreads();

            #pragma unroll 4
            for (int kt = 0; kt < 16; kt++) {
                const int kb = kt * 8;
                uint32_t af[2][4];
                #pragma unroll
                for (int mi = 0; mi < 2; mi++) {
                    int rb = (m_base + mi * 16 + g) * 132;
                    af[mi][0] = hs[rb +       kb + tg    ];
                    af[mi][1] = hs[rb + 8*132 + kb + tg  ];
                    af[mi][2] = hs[rb +       kb + tg + 4];
                    af[mi][3] = hs[rb + 8*132 + kb + tg + 4];
                }
                #pragma unroll
                for (int gt = 0; gt < 3; gt++) {
                    int kg = kbase + kb;
                    uint32_t b0r = Ws[((gt << 9) + kg + tg    ) * 16 + n8 + g];
                    uint32_t b1r = Ws[((gt << 9) + kg + tg + 4) * 16 + n8 + g];
                    #pragma unroll
                    for (int mi = 0; mi < 2; mi++) {
                        asm volatile(
                            "mma.sync.aligned.m16n8k8.row.col.f32.tf32.tf32.f32 "
                            "{%0,%1,%2,%3}, {%4,%5,%6,%7}, {%8,%9}, {%0,%1,%2,%3};"
                            : "+f"(c[mi][gt][0]), "+f"(c[mi][gt][1]),
                              "+f"(c[mi][gt][2]), "+f"(c[mi][gt][3])
                            : "r"(af[mi][0]), "r"(af[mi][1]), "r"(af[mi][2]), "r"(af[mi][3]),
                              "r"(b0r), "r"(b1r));
                    }
                }
            }
            __syncthreads();
        }

        #pragma unroll
        for (int mi = 0; mi < 2; mi++) {
            #pragma unroll
            for (int half = 0; half < 2; half++) {
                int j = mi * 2 + half;
                int q0 = half * 2;
                int bglob = b0 + m_base + j * 8 + g;
                float r0 = sigmoidf_(xr2[j].x + c[mi][0][q0]);
                float r1 = sigmoidf_(xr2[j].y + c[mi][0][q0 + 1]);
                float z0 = sigmoidf_(xz2[j].x + c[mi][1][q0]);
                float z1 = sigmoidf_(xz2[j].y + c[mi][1][q0 + 1]);
                float n0 = tanhf(xn2[j].x + r0 * (c[mi][2][q0]     + bh0));
                float n1 = tanhf(xn2[j].y + r1 * (c[mi][2][q0 + 1] + bh1));
                float2 o;
                o.x = (1.f - z0) * n0 + z0 * hp2[j].x;
                o.y = (1.f - z1) * n1 + z1 * hp2[j].y;
                *(float2*)(y + (size_t)t * BD + (size_t)bglob * DD + dcol) = o;
            }
        }

        grid_barrier(GRU_NBLK);
    }
}

// ---------------- actor head: logits = X@Wa + ba, availability mask ----------
__global__ __launch_bounds__(256) void head_gemm(
    const float* __restrict__ X, const float* __restrict__ Wa,
    const float* __restrict__ ba, const int* __restrict__ avail,
    float* __restrict__ out, int M)
{
    const int r = blockIdx.x * 8 + (threadIdx.x >> 5);
    const int a = threadIdx.x & 31;
    const float* xr = X + (size_t)r * DD;
    float acc = 0.f;
    #pragma unroll 8
    for (int k = 0; k < DD; k += 4) {
        float4 xv = *(const float4*)(xr + k);
        acc += xv.x * __ldg(Wa + (k + 0) * AA + a);
        acc += xv.y * __ldg(Wa + (k + 1) * AA + a);
        acc += xv.z * __ldg(Wa + (k + 2) * AA + a);
        acc += xv.w * __ldg(Wa + (k + 3) * AA + a);
    }
    float av = (float)avail[(size_t)r * AA + a];
    out[(size_t)r * AA + a] = acc + ba[a] - (1.f - av) * 1e10f;
}

__global__ void copy_kernel(const float* __restrict__ src, float* __restrict__ dst, int n)
{
    int i = blockIdx.x * blockDim.x + threadIdx.x;
    if (i < n) dst[i] = src[i];
}

// ---------------- host orchestration ----------------------------------------
extern "C" void kernel_launch(void* const* d_in, const int* in_sizes, int n_in,
                              void* d_out, int out_size)
{
    const float*          hidden = (const float*)d_in[0];
    const float*          obs    = (const float*)d_in[1];
    const int*            dones  = (const int*)d_in[2];   // bool promoted to int32
    const int*            avail  = (const int*)d_in[3];
    const float*          Wm     = (const float*)d_in[4];
    const float*          bm     = (const float*)d_in[5];
    const float*          lns    = (const float*)d_in[6];
    const float*          lnb    = (const float*)d_in[7];
    const float*          Wi     = (const float*)d_in[8];
    const float*          bi     = (const float*)d_in[9];
    const float*          Wh     = (const float*)d_in[10];
    const float*          bhn    = (const float*)d_in[11];
    const float*          Wo     = (const float*)d_in[12];
    const float*          bo     = (const float*)d_in[13];
    const float*          ln2s   = (const float*)d_in[14];
    const float*          ln2b   = (const float*)d_in[15];
    const float*          Wa     = (const float*)d_in[16];
    const float*          ba     = (const float*)d_in[17];
    float* out = (float*)d_out;

    float *bufA, *bufB, *Xbuf, *ybuf;
    cudaGetSymbolAddress((void**)&bufA, g_bufA);
    cudaGetSymbolAddress((void**)&bufB, g_bufB);
    cudaGetSymbolAddress((void**)&Xbuf, g_X);
    cudaGetSymbolAddress((void**)&ybuf, g_y);

    cudaFuncSetAttribute(gemm_big, cudaFuncAttributeMaxDynamicSharedMemorySize, G5_SMEM);

    const dim3 ggrid(DD / 128, MM / 128);   // (4, 512)
    float* bufs[2] = {bufA, bufB};

    // shift ncu capture index: launch #6 becomes the 3rd GEMM
    warmup_kernel<<<1, 32>>>();

    // --- MLP encoder: 3x (GEMM -> LN(+bias) -> ReLU), ping-pong buffers ---
    const float* cur = obs;
    for (int l = 0; l < LL; l++) {
        float* dst = bufs[l & 1];
        gemm_big<<<ggrid, 256, G5_SMEM>>>(cur, Wm + (size_t)l * DD * DD, dst, nullptr, MM, DD, DD);
        ln_bias_relu<<<MM, 128>>>(dst, bm + l * DD, lns + l * DD, lnb + l * DD);
        cur = dst;
    }

    // --- precompute input-gate activations for all t: X[g] = e @ Wi[g] + bi[g]
    for (int g = 0; g < 3; g++) {
        gemm_big<<<ggrid, 256, G5_SMEM>>>(cur, Wi + (size_t)g * DD * DD,
                                          Xbuf + (size_t)g * TBD, bi + g * DD, MM, DD, DD);
    }

    // --- persistent GRU scan: all 256 steps in one kernel ---
    static const int gru_smem = GRU_SMEM_WORDS * 4;   // 165888 bytes
    cudaFuncSetAttribute(gru_scan, cudaFuncAttributeMaxDynamicSharedMemorySize, gru_smem);
    gru_scan<<<GRU_NBLK, 256, gru_smem>>>(hidden, Xbuf, dones, Wh, bhn, ybuf);

    // --- actor head ---
    gemm_big<<<ggrid, 256, G5_SMEM>>>(ybuf, Wo, bufB, nullptr, MM, DD, DD);
    ln_bias_relu<<<MM, 128>>>(bufB, bo, ln2s, ln2b);

    bool has_hidden = (out_size >= (int)(BD + (size_t)MM * AA));
    float* logits_out = out + (has_hidden ? BD : 0);
    head_gemm<<<MM / 8, 256>>>(bufB, Wa, ba, avail, logits_out, MM);

    if (has_hidden) {
        copy_kernel<<<(BD + 255) / 256, 256>>>(ybuf + (size_t)(TT - 1) * BD, out, BD);
    }
}

// round 15
// speedup vs baseline: 1.2114x; 1.2114x over previous
#include <cuda_runtime.h>
#include <cuda_bf16.h>
#include <math.h>
#include <stdint.h>

#define TT 256
#define BB_ 256
#define DD 512
#define AA 32
#define LL 3
#define MM (TT*BB_)            // 65536 rows
#define TBD ((size_t)MM*DD)    // 33554432
#define BD (BB_*DD)            // 131072

// arch-specific feature gate: tcgen05 only exists in the sm_103a ("a") pass
#if defined(__CUDA_ARCH__) && (defined(__CUDA_ARCH_FEAT_SM103_ALL) || \
    (defined(__CUDA_ARCH_SPECIFIC__) && (__CUDA_ARCH_SPECIFIC__ == 1030)))
#define HAS_TCGEN05 1
#else
#define HAS_TCGEN05 0
#endif

// ---------------- scratch (device globals; no runtime allocation) -----------
__device__ float g_bufA[TT*BB_*DD];
__device__ float g_bufB[TT*BB_*DD];
__device__ float g_X[3ull*TT*BB_*DD];
__device__ float g_y[TT*BB_*DD];
__device__ __nv_bfloat16 g_Ahi[TT*BB_*DD];
__device__ __nv_bfloat16 g_Alo[TT*BB_*DD];
__device__ __nv_bfloat16 g_Whi[7*DD*DD];
__device__ __nv_bfloat16 g_Wlo[7*DD*DD];

// grid-barrier state for persistent GRU scan
__device__ unsigned g_bar_count = 0;
__device__ unsigned g_bar_gen   = 0;

// ---------------- generic helpers --------------------------------------------
__device__ __forceinline__ uint32_t f2tf32(float x) {
    uint32_t r;
    asm("cvt.rna.tf32.f32 %0, %1;" : "=r"(r) : "f"(x));
    return r;
}

__device__ __forceinline__ void cp_async16(uint32_t smem_addr, const void* gmem_ptr) {
    asm volatile("cp.async.cg.shared.global [%0], [%1], 16;" :: "r"(smem_addr), "l"(gmem_ptr));
}

__device__ __forceinline__ unsigned ld_acquire_u32(unsigned* p) {
    unsigned v;
    asm volatile("ld.acquire.gpu.u32 %0, [%1];" : "=r"(v) : "l"(p) : "memory");
    return v;
}

// release/acquire grid barrier; all NBLK blocks must be co-resident
__device__ __forceinline__ void grid_barrier(unsigned nblk) {
    __threadfence();
    __syncthreads();
    if (threadIdx.x == 0) {
        unsigned gen = *((volatile unsigned*)&g_bar_gen);   // read BEFORE arrive
        unsigned arrived = atomicAdd(&g_bar_count, 1u);
        if (arrived == nblk - 1) {
            g_bar_count = 0;
            __threadfence();
            atomicAdd(&g_bar_gen, 1u);
        } else {
            while (ld_acquire_u32(&g_bar_gen) == gen) { __nanosleep(64); }
        }
    }
    __syncthreads();
}

__device__ __forceinline__ uint32_t smem_to_u32(const void* smem_ptr) {
    uint32_t addr;
    asm("{ .reg .u64 tmp; cvta.to.shared.u64 tmp, %1; cvt.u32.u64 %0, tmp; }"
        : "=r"(addr) : "l"(smem_ptr));
    return addr;
}

#define MBAR_INIT(mbar, cnt) \
    asm volatile("mbarrier.init.shared.b64 [%0], %1;" \
        :: "r"((uint32_t)(mbar)), "r"((uint32_t)(cnt)) : "memory")

#define MBAR_WAIT_PARITY(mbar_addr, parity) do { \
    uint32_t _m = (uint32_t)(mbar_addr); \
    uint32_t _p = (uint32_t)(parity); \
    uint32_t _done; \
    asm volatile( \
        "{\n\t.reg .pred p;\n\t" \
        "mbarrier.try_wait.parity.acquire.cta.shared::cta.b64 p, [%1], %2;\n\t" \
        "selp.b32 %0, 1, 0, p;\n\t}" \
        : "=r"(_done) : "r"(_m), "r"(_p) : "memory"); \
    if (!_done) { \
        asm volatile( \
            "{\n\t.reg .pred P1;\n\t" \
            "WAIT_LOOP_%=:\n\t" \
            "mbarrier.try_wait.parity.acquire.cta.shared::cta.b64 P1, [%0], %1, 0x989680;\n\t" \
            "@P1 bra.uni WAIT_DONE_%=;\n\t" \
            "bra.uni WAIT_LOOP_%=;\n\t" \
            "WAIT_DONE_%=:\n\t}" \
            :: "r"(_m), "r"(_p) : "memory"); \
    } \
} while(0)

#if HAS_TCGEN05
// ---------------- tcgen05 helpers (sm_103a pass only) ------------------------
__device__ __forceinline__ uint32_t elect_one_pred() {
    uint32_t pred;
    asm volatile(
        "{\n\t.reg .pred p;\n\telect.sync _|p, 0xFFFFFFFF;\n\tselp.b32 %0, 1, 0, p;\n\t}"
        : "=r"(pred));
    return pred;
}

#define TCG_ALLOC(smem_result_addr, nCols) \
    asm volatile("tcgen05.alloc.cta_group::1.sync.aligned.shared::cta.b32 [%0], %1;" \
        :: "r"((uint32_t)(smem_result_addr)), "r"((uint32_t)(nCols)) : "memory")
#define TCG_DEALLOC(tmem_addr, nCols) \
    asm volatile("tcgen05.dealloc.cta_group::1.sync.aligned.b32 %0, %1;" \
        :: "r"(tmem_addr), "r"((uint32_t)(nCols)))
#define TCG_COMMIT(mbar) \
    asm volatile("tcgen05.commit.cta_group::1.mbarrier::arrive::one.shared::cluster.b64 [%0];" \
        :: "r"((uint32_t)(mbar)) : "memory")
#define TCG_FENCE_BEFORE() asm volatile("tcgen05.fence::before_thread_sync;" ::: "memory")
#define TCG_FENCE_AFTER()  asm volatile("tcgen05.fence::after_thread_sync;" ::: "memory")
#define FENCE_PROXY_ASYNC() asm volatile("fence.proxy.async.shared::cta;" ::: "memory")
#define TCG_WAIT_LD() asm volatile("tcgen05.wait::ld.sync.aligned;" ::: "memory")

#define TCG_LD_32X32B_X32(r, tmem_addr) \
    asm volatile( \
        "tcgen05.ld.sync.aligned.32x32b.x32.b32 " \
        "{%0, %1, %2, %3, %4, %5, %6, %7, " \
        " %8, %9, %10, %11, %12, %13, %14, %15, " \
        " %16, %17, %18, %19, %20, %21, %22, %23, " \
        " %24, %25, %26, %27, %28, %29, %30, %31}, [%32];" \
        : "=r"((r)[0]),  "=r"((r)[1]),  "=r"((r)[2]),  "=r"((r)[3]), \
          "=r"((r)[4]),  "=r"((r)[5]),  "=r"((r)[6]),  "=r"((r)[7]), \
          "=r"((r)[8]),  "=r"((r)[9]),  "=r"((r)[10]), "=r"((r)[11]), \
          "=r"((r)[12]), "=r"((r)[13]), "=r"((r)[14]), "=r"((r)[15]), \
          "=r"((r)[16]), "=r"((r)[17]), "=r"((r)[18]), "=r"((r)[19]), \
          "=r"((r)[20]), "=r"((r)[21]), "=r"((r)[22]), "=r"((r)[23]), \
          "=r"((r)[24]), "=r"((r)[25]), "=r"((r)[26]), "=r"((r)[27]), \
          "=r"((r)[28]), "=r"((r)[29]), "=r"((r)[30]), "=r"((r)[31]) \
        : "r"(tmem_addr))

__device__ __forceinline__ void tcg_mma_f16_ss(
    uint32_t d_tmem, uint64_t a_desc, uint64_t b_desc, uint32_t idesc, bool en)
{
    uint32_t e = en ? 1u : 0u;
    asm volatile(
        "{\n\t.reg .pred p;\n\tsetp.ne.u32 p, %4, 0;\n\t"
        "tcgen05.mma.cta_group::1.kind::f16 [%0], %1, %2, %3, {%5, %5, %5, %5}, p;\n\t}"
        :: "r"(d_tmem), "l"(a_desc), "l"(b_desc), "r"(idesc), "r"(e), "r"(0u)
        : "memory");
}
#endif  // HAS_TCGEN05

// SW128 K-major smem descriptor: layout=2, version=1(Blackwell), SBO=64, LBO=1
static constexpr uint64_t SMEM_DESC_BASE_SW128 =
    (uint64_t(2) << 61) | (uint64_t(1) << 46) | (uint64_t(64) << 32) | (uint64_t(1) << 16);
#define MAKE_DESC(addr) (SMEM_DESC_BASE_SW128 | ((uint64_t)((addr) >> 4) & 0x3FFF))
#define SWZ128(off) ((off) ^ (((off) >> 3) & 0x70))

// idesc kind::f16: dtype F32(1<<4), atype BF16(1<<7), btype BF16(1<<10),
// N=128 -> 16<<17, M=128 -> 8<<24   (formula validated by test_mma.cu)
static constexpr uint32_t IDESC_BF16_128x128 =
    (1u << 4) | (1u << 7) | (1u << 10) | (16u << 17) | (8u << 24);

// ---------------- conversion kernels ------------------------------------------
// fp32 -> split hi/lo bf16 arrays (elementwise)
__global__ __launch_bounds__(256) void convert_act(
    const float* __restrict__ src,
    __nv_bfloat16* __restrict__ hi, __nv_bfloat16* __restrict__ lo, int n4)
{
    int i = blockIdx.x * blockDim.x + threadIdx.x;
    if (i >= n4) return;
    float4 v = ((const float4*)src)[i];
    __nv_bfloat16 h0 = __float2bfloat16(v.x), h1 = __float2bfloat16(v.y),
                  h2 = __float2bfloat16(v.z), h3 = __float2bfloat16(v.w);
    __nv_bfloat16 l0 = __float2bfloat16(v.x - __bfloat162float(h0));
    __nv_bfloat16 l1 = __float2bfloat16(v.y - __bfloat162float(h1));
    __nv_bfloat16 l2 = __float2bfloat16(v.z - __bfloat162float(h2));
    __nv_bfloat16 l3 = __float2bfloat16(v.w - __bfloat162float(h3));
    ((ushort4*)hi)[i] = make_ushort4(__bfloat16_as_ushort(h0), __bfloat16_as_ushort(h1),
                                     __bfloat16_as_ushort(h2), __bfloat16_as_ushort(h3));
    ((ushort4*)lo)[i] = make_ushort4(__bfloat16_as_ushort(l0), __bfloat16_as_ushort(l1),
                                     __bfloat16_as_ushort(l2), __bfloat16_as_ushort(l3));
}

// transpose + split all 7 weight matrices: W[k][n] -> Wt_hi/lo[m][n][k]
__global__ __launch_bounds__(256) void convert_wt(
    const float* __restrict__ Wm, const float* __restrict__ Wi,
    const float* __restrict__ Wo,
    __nv_bfloat16* __restrict__ hi, __nv_bfloat16* __restrict__ lo)
{
    __shared__ float tile[32][33];
    const int m = blockIdx.z;
    const float* src = (m < 3) ? (Wm + (size_t)m * DD * DD)
                    : (m < 6) ? (Wi + (size_t)(m - 3) * DD * DD) : Wo;
    const int k0 = blockIdx.y * 32, n0 = blockIdx.x * 32;
    const int tx = threadIdx.x & 31, ty = threadIdx.x >> 5;   // 32 x 8
    #pragma unroll
    for (int r = 0; r < 32; r += 8)
        tile[ty + r][tx] = src[(size_t)(k0 + ty + r) * DD + n0 + tx];
    __syncthreads();
    #pragma unroll
    for (int r = 0; r < 32; r += 8) {
        float v = tile[tx][ty + r];              // = src[k0+tx][n0+ty+r]
        __nv_bfloat16 h = __float2bfloat16(v);
        __nv_bfloat16 l = __float2bfloat16(v - __bfloat162float(h));
        size_t o = (size_t)m * DD * DD + (size_t)(n0 + ty + r) * DD + k0 + tx;
        hi[o] = h; lo[o] = l;
    }
}

// ---------------- tcgen05 split-bf16 GEMM, cp.async 3-stage -------------------
// C[M,512] = A @ W (+bias); A given as hi/lo bf16 [M][512]; W as hi/lo bf16
// TRANSPOSED [n][k]. D += Ahi*Bhi + Ahi*Blo + Alo*Bhi (fp32 TMEM acc).
// smem: hdr 1KB (tmem ptr + 3 mbars) + 3 stages x 64KB (Ahi/Alo/Bhi/Blo tiles
// of 128 rows x 128B SW128).
#define ST_BYTES 65536
#define ST_ALO   16384
#define ST_BHI   32768
#define ST_BLO   49152
#define TC_SMEM  (1024 + 3*ST_BYTES)    // 197632

__global__ __launch_bounds__(256, 1) void gemm_tc(
    const __nv_bfloat16* __restrict__ Ahi, const __nv_bfloat16* __restrict__ Alo,
    const __nv_bfloat16* __restrict__ Bhi, const __nv_bfloat16* __restrict__ Blo,
    float* __restrict__ C, const float* __restrict__ bias)
{
#if HAS_TCGEN05
    extern __shared__ char smem[];
    const uint32_t smem_base = smem_to_u32(smem);
    const int tid = threadIdx.x;
    const int wid = tid >> 5, lane = tid & 31;
    const int bx = blockIdx.x, by = blockIdx.y;    // n tile (0..3), m tile

    if (wid == 0) TCG_ALLOC(smem_base + 0, 128);
    if (tid == 0) {
        MBAR_INIT(smem_base + 8,  1);
        MBAR_INIT(smem_base + 16, 1);
        MBAR_INIT(smem_base + 24, 1);
    }
    __syncthreads();
    uint32_t tmem_base;
    asm volatile("ld.shared.b32 %0, [%1];" : "=r"(tmem_base) : "r"(smem_base + 0));

    // per-thread load coords: 2 threads per tile row, 4x16B units each
    const int row = tid >> 1;                  // 0..127
    const int ub  = (tid & 1) * 4;             // 16B unit base (0 or 4)
    const size_t a_goff = ((size_t)(by * 128 + row) * DD) * 2;  // bytes
    const size_t b_goff = ((size_t)(bx * 128 + row) * DD) * 2;  // bytes (B row = n)

    const char* pAhi = (const char*)Ahi + a_goff;
    const char* pAlo = (const char*)Alo + a_goff;
    const char* pBhi = (const char*)Bhi + b_goff;
    const char* pBlo = (const char*)Blo + b_goff;

    auto issue_load = [&](int c, int s) {
        uint32_t st = smem_base + 1024 + s * ST_BYTES;
        int cb = c * 128;   // byte offset of k-chunk within a row
        #pragma unroll
        for (int i = 0; i < 4; i++) {
            int u = ub + i;
            uint32_t dsw = SWZ128((uint32_t)(row * 128 + u * 16));
            int go = cb + u * 16;
            cp_async16(st +           dsw, pAhi + go);
            cp_async16(st + ST_ALO  + dsw, pAlo + go);
            cp_async16(st + ST_BHI  + dsw, pBhi + go);
            cp_async16(st + ST_BLO  + dsw, pBlo + go);
        }
        asm volatile("cp.async.commit_group;");
    };

    // prologue: 3 stages in flight
    issue_load(0, 0);
    issue_load(1, 1);
    issue_load(2, 2);

    int phase[3] = {0, 0, 0};

    #pragma unroll
    for (int c = 0; c < 8; c++) {
        const int s = c - (c >= 6 ? 6 : (c >= 3 ? 3 : 0));   // c % 3
        // data arrival for chunk c
        if (c <= 5)      asm volatile("cp.async.wait_group 2;");
        else if (c == 6) asm volatile("cp.async.wait_group 1;");
        else             asm volatile("cp.async.wait_group 0;");
        __syncthreads();
        FENCE_PROXY_ASYNC();

        if (wid == 0 && elect_one_pred()) {
            uint32_t st = smem_base + 1024 + s * ST_BYTES;
            uint64_t ah = MAKE_DESC(st);
            uint64_t al = MAKE_DESC(st + ST_ALO);
            uint64_t bh = MAKE_DESC(st + ST_BHI);
            uint64_t bl = MAKE_DESC(st + ST_BLO);
            #pragma unroll
            for (int ks = 0; ks < 4; ks++) {     // K=16 bf16 per mma, +2 units/step
                uint64_t off = (uint64_t)(ks * 2);
                tcg_mma_f16_ss(tmem_base, ah + off, bh + off, IDESC_BF16_128x128,
                               !(c == 0 && ks == 0));
                tcg_mma_f16_ss(tmem_base, ah + off, bl + off, IDESC_BF16_128x128, true);
                tcg_mma_f16_ss(tmem_base, al + off, bh + off, IDESC_BF16_128x128, true);
            }
            TCG_COMMIT(smem_base + 8 + s * 8);
        }

        if (c + 3 < 8) {
            // slot s reused by chunk c+3: wait mma of chunk c to finish reading
            MBAR_WAIT_PARITY(smem_base + 8 + s * 8, phase[s]);
            phase[s] ^= 1;
            issue_load(c + 3, s);
        }
    }

    // final completion waits (remaining commit per slot)
    MBAR_WAIT_PARITY(smem_base + 8,  phase[0]);
    MBAR_WAIT_PARITY(smem_base + 16, phase[1]);
    MBAR_WAIT_PARITY(smem_base + 24, phase[2]);
    TCG_FENCE_AFTER();
    __syncthreads();

    // ---- epilogue: TMEM -> smem (padded) -> coalesced gmem ----
    float* ds = (float*)(smem + 1024);      // 128 x 132 fp32 (stages dead)
    if (wid < 4) {
        int r0 = wid * 32 + lane;
        #pragma unroll
        for (int r = 0; r < 4; r++) {
            uint32_t regs[32];
            TCG_LD_32X32B_X32(regs, tmem_base + r * 32);
            TCG_WAIT_LD();
            #pragma unroll
            for (int q = 0; q < 32; q++)
                ds[r0 * 132 + r * 32 + q] = __uint_as_float(regs[q]);
        }
        TCG_FENCE_BEFORE();
    }
    __syncthreads();
    {
        int r0 = tid >> 1;
        int cb = (tid & 1) * 64;
        float* crow = C + (size_t)(by * 128 + r0) * DD + bx * 128 + cb;
        #pragma unroll
        for (int i = 0; i < 16; i++) {
            float4 v = *(float4*)(ds + r0 * 132 + cb + i * 4);
            if (bias) {
                float4 b = *(const float4*)(bias + bx * 128 + cb + i * 4);
                v.x += b.x; v.y += b.y; v.z += b.z; v.w += b.w;
            }
            *(float4*)(crow + i * 4) = v;
        }
    }
    __syncthreads();
    if (wid == 0) TCG_DEALLOC(tmem_base, 128);

#else
    // compile-only correctness fallback (sm_103a cubin is selected at runtime)
    const int bx = blockIdx.x, by = blockIdx.y, tid = threadIdx.x;
    int r0 = (tid >> 4) * 8;
    int c0 = (tid & 15) * 8;
    for (int i = 0; i < 8; i++)
        for (int j = 0; j < 8; j++) {
            int m = by * 128 + r0 + i, n = bx * 128 + c0 + j;
            float acc = 0.f;
            for (int k = 0; k < DD; k++) {
                float a = __bfloat162float(Ahi[(size_t)m * DD + k]) +
                          __bfloat162float(Alo[(size_t)m * DD + k]);
                float b = __bfloat162float(Bhi[(size_t)n * DD + k]) +
                          __bfloat162float(Blo[(size_t)n * DD + k]);
                acc += a * b;
            }
            if (bias) acc += bias[n];
            C[(size_t)m * DD + n] = acc;
        }
#endif
}

// ---------------- tiny launch-index shifter (ncu -s 5 lands on gemm #2) ------
__global__ void warmup_kernel() { if (threadIdx.x == 0) g_bar_count = 0; }

// ---------------- LayerNorm(+bias)+ReLU, fp32 in -> split bf16 out -----------
__global__ __launch_bounds__(128) void ln_bias_relu_bf16(
    const float* __restrict__ X, const float* __restrict__ bias,
    const float* __restrict__ gamma, const float* __restrict__ beta,
    __nv_bfloat16* __restrict__ hi, __nv_bfloat16* __restrict__ lo)
{
    const int row = blockIdx.x;
    const int tid = threadIdx.x;
    const float* xp = X + (size_t)row * DD + tid * 4;
    float4 v = *(const float4*)xp;
    float4 bb = *(const float4*)(bias + tid * 4);
    v.x += bb.x; v.y += bb.y; v.z += bb.z; v.w += bb.w;

    float s  = v.x + v.y + v.z + v.w;
    float sq = v.x*v.x + v.y*v.y + v.z*v.z + v.w*v.w;
    #pragma unroll
    for (int o = 16; o > 0; o >>= 1) {
        s  += __shfl_down_sync(0xffffffffu, s,  o);
        sq += __shfl_down_sync(0xffffffffu, sq, o);
    }
    __shared__ float ws[4], wq[4];
    if ((tid & 31) == 0) { ws[tid >> 5] = s; wq[tid >> 5] = sq; }
    __syncthreads();
    float st = ws[0] + ws[1] + ws[2] + ws[3];
    float qt = wq[0] + wq[1] + wq[2] + wq[3];
    float mean = st * (1.f / DD);
    float var  = qt * (1.f / DD) - mean * mean;
    float inv  = rsqrtf(var + 1e-6f);

    float4 g = *(const float4*)(gamma + tid * 4);
    float4 b2 = *(const float4*)(beta + tid * 4);
    float o0 = fmaxf((v.x - mean) * inv * g.x + b2.x, 0.f);
    float o1 = fmaxf((v.y - mean) * inv * g.y + b2.y, 0.f);
    float o2 = fmaxf((v.z - mean) * inv * g.z + b2.z, 0.f);
    float o3 = fmaxf((v.w - mean) * inv * g.w + b2.w, 0.f);

    __nv_bfloat16 h0 = __float2bfloat16(o0), h1 = __float2bfloat16(o1),
                  h2 = __float2bfloat16(o2), h3 = __float2bfloat16(o3);
    __nv_bfloat16 l0 = __float2bfloat16(o0 - __bfloat162float(h0));
    __nv_bfloat16 l1 = __float2bfloat16(o1 - __bfloat162float(h1));
    __nv_bfloat16 l2 = __float2bfloat16(o2 - __bfloat162float(h2));
    __nv_bfloat16 l3 = __float2bfloat16(o3 - __bfloat162float(h3));
    ((ushort4*)(hi + (size_t)row * DD))[tid] =
        make_ushort4(__bfloat16_as_ushort(h0), __bfloat16_as_ushort(h1),
                     __bfloat16_as_ushort(h2), __bfloat16_as_ushort(h3));
    ((ushort4*)(lo + (size_t)row * DD))[tid] =
        make_ushort4(__bfloat16_as_ushort(l0), __bfloat16_as_ushort(l1),
                     __bfloat16_as_ushort(l2), __bfloat16_as_ushort(l3));
}

// ---------------- LayerNorm(+bias)+ReLU fp32 in place (head) -----------------
__global__ __launch_bounds__(128) void ln_bias_relu(
    float* __restrict__ X, const float* __restrict__ bias,
    const float* __restrict__ gamma, const float* __restrict__ beta)
{
    const int row = blockIdx.x;
    const int tid = threadIdx.x;
    float* xp = X + (size_t)row * DD + tid * 4;
    float4 v = *(float4*)xp;
    float4 bb = *(const float4*)(bias + tid * 4);
    v.x += bb.x; v.y += bb.y; v.z += bb.z; v.w += bb.w;

    float s  = v.x + v.y + v.z + v.w;
    float sq = v.x*v.x + v.y*v.y + v.z*v.z + v.w*v.w;
    #pragma unroll
    for (int o = 16; o > 0; o >>= 1) {
        s  += __shfl_down_sync(0xffffffffu, s,  o);
        sq += __shfl_down_sync(0xffffffffu, sq, o);
    }
    __shared__ float ws[4], wq[4];
    if ((tid & 31) == 0) { ws[tid >> 5] = s; wq[tid >> 5] = sq; }
    __syncthreads();
    float st = ws[0] + ws[1] + ws[2] + ws[3];
    float qt = wq[0] + wq[1] + wq[2] + wq[3];
    float mean = st * (1.f / DD);
    float var  = qt * (1.f / DD) - mean * mean;
    float inv  = rsqrtf(var + 1e-6f);

    float4 g = *(const float4*)(gamma + tid * 4);
    float4 b2 = *(const float4*)(beta + tid * 4);
    float4 o;
    o.x = fmaxf((v.x - mean) * inv * g.x + b2.x, 0.f);
    o.y = fmaxf((v.y - mean) * inv * g.y + b2.y, 0.f);
    o.z = fmaxf((v.z - mean) * inv * g.z + b2.z, 0.f);
    o.w = fmaxf((v.w - mean) * inv * g.w + b2.w, 0.f);
    *(float4*)xp = o;
}

// ---------------- persistent GRU scan (tf32 mma + grid barrier) --------------
#define GRU_NBLK 64
#define GRU_SMEM_WORDS (3*512*16 + 128*132)    // Ws + hs = 41472 words

__device__ __forceinline__ float sigmoidf_(float x) { return 1.f / (1.f + expf(-x)); }

__global__ __launch_bounds__(256, 1) void gru_scan(
    const float* __restrict__ hidden,
    const float* __restrict__ X,
    const int* __restrict__ dones,
    const float* __restrict__ Wh,
    const float* __restrict__ bhn,
    float* __restrict__ y)
{
    extern __shared__ uint32_t smem_u[];
    uint32_t* Ws = smem_u;
    uint32_t* hs = smem_u + 3*512*16;

    const int bi = blockIdx.x;
    const int nb = bi >> 5;
    const int nd = bi & 31;
    const int b0 = nb * 128;
    const int d0 = nd * 16;

    const int tid  = threadIdx.x;
    const int warp = tid >> 5, lane = tid & 31;
    const int wm = warp & 3, wn = warp >> 2;
    const int m_base = wm * 32;
    const int n8 = wn * 8;
    const int g  = lane >> 2;
    const int tg = lane & 3;

    #pragma unroll 4
    for (int i = 0; i < 24; i++) {
        int q = tid + i * 256;
        int gate = q >> 11;
        int rem  = q & 2047;
        int k    = rem >> 2;
        int dl4  = (rem & 3) * 4;
        float4 w = *(const float4*)(Wh + ((size_t)gate * 512 + k) * 512 + d0 + dl4);
        uint4 u = make_uint4(f2tf32(w.x), f2tf32(w.y), f2tf32(w.z), f2tf32(w.w));
        *(uint4*)(&Ws[((gate << 9) + k) * 16 + dl4]) = u;
    }

    const int dcol = d0 + n8 + tg * 2;
    const float bh0 = bhn[dcol], bh1 = bhn[dcol + 1];
    __syncthreads();

    for (int t = 0; t < TT; t++) {
        const float* hprev = (t == 0) ? hidden : (y + (size_t)(t - 1) * BD);
        const int* dn = dones + (size_t)t * BB_;

        float2 xr2[4], xz2[4], xn2[4], hp2[4];
        #pragma unroll
        for (int j = 0; j < 4; j++) {
            int bglob = b0 + m_base + j * 8 + g;
            int df = dn[bglob];
            size_t gi = (size_t)bglob * DD + dcol;
            hp2[j] = df ? make_float2(0.f, 0.f) : *(const float2*)(hprev + gi);
            size_t xi = (size_t)t * BD + gi;
            xr2[j] = *(const float2*)(X + xi);
            xz2[j] = *(const float2*)(X + TBD + xi);
            xn2[j] = *(const float2*)(X + 2 * TBD + xi);
        }

        float c[2][3][4];
        #pragma unroll
        for (int mi = 0; mi < 2; mi++)
            #pragma unroll
            for (int gt = 0; gt < 3; gt++)
                #pragma unroll
                for (int q = 0; q < 4; q++) c[mi][gt][q] = 0.f;

        for (int kc = 0; kc < 4; kc++) {
            const int kbase = kc * 128;
            #pragma unroll 4
            for (int i = 0; i < 16; i++) {
                int linear = tid + i * 256;
                int row = linear >> 5;
                int c4  = (linear & 31) * 4;
                int gb  = b0 + row;
                float4 v;
                if (dn[gb]) v = make_float4(0.f, 0.f, 0.f, 0.f);
                else v = *(const float4*)(hprev + (size_t)gb * DD + kbase + c4);
                uint4 u = make_uint4(f2tf32(v.x), f2tf32(v.y), f2tf32(v.z), f2tf32(v.w));
                *(uint4*)(&hs[row * 132 + c4]) = u;
            }
            __syncthreads();

            #pragma unroll 4
            for (int kt = 0; kt < 16; kt++) {
                const int kb = kt * 8;
                uint32_t af[2][4];
                #pragma unroll
                for (int mi = 0; mi < 2; mi++) {
                    int rb = (m_base + mi * 16 + g) * 132;
                    af[mi][0] = hs[rb +       kb + tg    ];
                    af[mi][1] = hs[rb + 8*132 + kb + tg  ];
                    af[mi][2] = hs[rb +       kb + tg + 4];
                    af[mi][3] = hs[rb + 8*132 + kb + tg + 4];
                }
                #pragma unroll
                for (int gt = 0; gt < 3; gt++) {
                    int kg = kbase + kb;
                    uint32_t b0r = Ws[((gt << 9) + kg + tg    ) * 16 + n8 + g];
                    uint32_t b1r = Ws[((gt << 9) + kg + tg + 4) * 16 + n8 + g];
                    #pragma unroll
                    for (int mi = 0; mi < 2; mi++) {
                        asm volatile(
                            "mma.sync.aligned.m16n8k8.row.col.f32.tf32.tf32.f32 "
                            "{%0,%1,%2,%3}, {%4,%5,%6,%7}, {%8,%9}, {%0,%1,%2,%3};"
                            : "+f"(c[mi][gt][0]), "+f"(c[mi][gt][1]),
                              "+f"(c[mi][gt][2]), "+f"(c[mi][gt][3])
                            : "r"(af[mi][0]), "r"(af[mi][1]), "r"(af[mi][2]), "r"(af[mi][3]),
                              "r"(b0r), "r"(b1r));
                    }
                }
            }
            __syncthreads();
        }

        #pragma unroll
        for (int mi = 0; mi < 2; mi++) {
            #pragma unroll
            for (int half = 0; half < 2; half++) {
                int j = mi * 2 + half;
                int q0 = half * 2;
                int bglob = b0 + m_base + j * 8 + g;
                float r0 = sigmoidf_(xr2[j].x + c[mi][0][q0]);
                float r1 = sigmoidf_(xr2[j].y + c[mi][0][q0 + 1]);
                float z0 = sigmoidf_(xz2[j].x + c[mi][1][q0]);
                float z1 = sigmoidf_(xz2[j].y + c[mi][1][q0 + 1]);
                float n0 = tanhf(xn2[j].x + r0 * (c[mi][2][q0]     + bh0));
                float n1 = tanhf(xn2[j].y + r1 * (c[mi][2][q0 + 1] + bh1));
                float2 o;
                o.x = (1.f - z0) * n0 + z0 * hp2[j].x;
                o.y = (1.f - z1) * n1 + z1 * hp2[j].y;
                *(float2*)(y + (size_t)t * BD + (size_t)bglob * DD + dcol) = o;
            }
        }

        grid_barrier(GRU_NBLK);
    }
}

// ---------------- actor head: logits = X@Wa + ba, availability mask ----------
__global__ __launch_bounds__(256) void head_gemm(
    const float* __restrict__ X, const float* __restrict__ Wa,
    const float* __restrict__ ba, const int* __restrict__ avail,
    float* __restrict__ out, int M)
{
    const int r = blockIdx.x * 8 + (threadIdx.x >> 5);
    const int a = threadIdx.x & 31;
    const float* xr = X + (size_t)r * DD;
    float acc = 0.f;
    #pragma unroll 8
    for (int k = 0; k < DD; k += 4) {
        float4 xv = *(const float4*)(xr + k);
        acc += xv.x * __ldg(Wa + (k + 0) * AA + a);
        acc += xv.y * __ldg(Wa + (k + 1) * AA + a);
        acc += xv.z * __ldg(Wa + (k + 2) * AA + a);
        acc += xv.w * __ldg(Wa + (k + 3) * AA + a);
    }
    float av = (float)avail[(size_t)r * AA + a];
    out[(size_t)r * AA + a] = acc + ba[a] - (1.f - av) * 1e10f;
}

__global__ void copy_kernel(const float* __restrict__ src, float* __restrict__ dst, int n)
{
    int i = blockIdx.x * blockDim.x + threadIdx.x;
    if (i < n) dst[i] = src[i];
}

// ---------------- host orchestration ----------------------------------------
extern "C" void kernel_launch(void* const* d_in, const int* in_sizes, int n_in,
                              void* d_out, int out_size)
{
    const float*          hidden = (const float*)d_in[0];
    const float*          obs    = (const float*)d_in[1];
    const int*            dones  = (const int*)d_in[2];   // bool promoted to int32
    const int*            avail  = (const int*)d_in[3];
    const float*          Wm     = (const float*)d_in[4];
    const float*          bm     = (const float*)d_in[5];
    const float*          lns    = (const float*)d_in[6];
    const float*          lnb    = (const float*)d_in[7];
    const float*          Wi     = (const float*)d_in[8];
    const float*          bi     = (const float*)d_in[9];
    const float*          Wh     = (const float*)d_in[10];
    const float*          bhn    = (const float*)d_in[11];
    const float*          Wo     = (const float*)d_in[12];
    const float*          bo     = (const float*)d_in[13];
    const float*          ln2s   = (const float*)d_in[14];
    const float*          ln2b   = (const float*)d_in[15];
    const float*          Wa     = (const float*)d_in[16];
    const float*          ba     = (const float*)d_in[17];
    float* out = (float*)d_out;

    float *bufA, *bufB, *Xbuf, *ybuf;
    __nv_bfloat16 *Ahi, *Alo, *Whi, *Wlo;
    cudaGetSymbolAddress((void**)&bufA, g_bufA);
    cudaGetSymbolAddress((void**)&bufB, g_bufB);
    cudaGetSymbolAddress((void**)&Xbuf, g_X);
    cudaGetSymbolAddress((void**)&ybuf, g_y);
    cudaGetSymbolAddress((void**)&Ahi, g_Ahi);
    cudaGetSymbolAddress((void**)&Alo, g_Alo);
    cudaGetSymbolAddress((void**)&Whi, g_Whi);
    cudaGetSymbolAddress((void**)&Wlo, g_Wlo);

    cudaFuncSetAttribute(gemm_tc, cudaFuncAttributeMaxDynamicSharedMemorySize, TC_SMEM);

    const dim3 ggrid(DD / 128, MM / 128);   // (4, 512)
    const int WSZ = DD * DD;                // 262144

    // launch order: 0 warmup, 1 convert_wt, 2 convert_act, 3 g1, 4 ln, 5 g2 (ncu -s5)
    warmup_kernel<<<1, 32>>>();
    convert_wt<<<dim3(16, 16, 7), 256>>>(Wm, Wi, Wo, Whi, Wlo);
    convert_act<<<(int)(TBD / 4 / 256), 256>>>(obs, Ahi, Alo, (int)(TBD / 4));

    // --- MLP encoder: 3x (GEMM -> LN+split), A pair ping-ponged in place ---
    for (int l = 0; l < LL; l++) {
        gemm_tc<<<ggrid, 256, TC_SMEM>>>(Ahi, Alo,
                                         Whi + (size_t)l * WSZ, Wlo + (size_t)l * WSZ,
                                         bufA, nullptr);
        ln_bias_relu_bf16<<<MM, 128>>>(bufA, bm + l * DD, lns + l * DD, lnb + l * DD,
                                       Ahi, Alo);
    }

    // --- input-gate activations: X[g] = e @ Wi[g] + bi[g] (e = Ahi/Alo pair)
    for (int g = 0; g < 3; g++) {
        gemm_tc<<<ggrid, 256, TC_SMEM>>>(Ahi, Alo,
                                         Whi + (size_t)(3 + g) * WSZ,
                                         Wlo + (size_t)(3 + g) * WSZ,
                                         Xbuf + (size_t)g * TBD, bi + g * DD);
    }

    // --- persistent GRU scan: all 256 steps in one kernel ---
    static const int gru_smem = GRU_SMEM_WORDS * 4;   // 165888 bytes
    cudaFuncSetAttribute(gru_scan, cudaFuncAttributeMaxDynamicSharedMemorySize, gru_smem);
    gru_scan<<<GRU_NBLK, 256, gru_smem>>>(hidden, Xbuf, dones, Wh, bhn, ybuf);

    // --- actor head: convert y, GEMM Wo, LN, small GEMM + mask ---
    convert_act<<<(int)(TBD / 4 / 256), 256>>>(ybuf, Ahi, Alo, (int)(TBD / 4));
    gemm_tc<<<ggrid, 256, TC_SMEM>>>(Ahi, Alo,
                                     Whi + (size_t)6 * WSZ, Wlo + (size_t)6 * WSZ,
                                     bufB, nullptr);
    ln_bias_relu<<<MM, 128>>>(bufB, bo, ln2s, ln2b);

    bool has_hidden = (out_size >= (int)(BD + (size_t)MM * AA));
    float* logits_out = out + (has_hidden ? BD : 0);
    head_gemm<<<MM / 8, 256>>>(bufB, Wa, ba, avail, logits_out, MM);

    if (has_hidden) {
        copy_kernel<<<(BD + 255) / 256, 256>>>(ybuf + (size_t)(TT - 1) * BD, out, BD);
    }
}

// round 16
// speedup vs baseline: 1.6299x; 1.3455x over previous
#include <cuda_runtime.h>
#include <cuda_bf16.h>
#include <math.h>
#include <stdint.h>

#define TT 256
#define BB_ 256
#define DD 512
#define AA 32
#define LL 3
#define MM (TT*BB_)            // 65536 rows
#define TBD ((size_t)MM*DD)    // 33554432
#define BD (BB_*DD)            // 131072

// arch-specific feature gate: tcgen05 only exists in the sm_103a ("a") pass
#if defined(__CUDA_ARCH__) && (defined(__CUDA_ARCH_FEAT_SM103_ALL) || \
    (defined(__CUDA_ARCH_SPECIFIC__) && (__CUDA_ARCH_SPECIFIC__ == 1030)))
#define HAS_TCGEN05 1
#else
#define HAS_TCGEN05 0
#endif

// ---------------- scratch (device globals; no runtime allocation) -----------
__device__ float g_bufA[TT*BB_*DD];
__device__ float g_bufB[TT*BB_*DD];
__device__ float g_X[3ull*TT*BB_*DD];
__device__ float g_y[TT*BB_*DD];
__device__ __nv_bfloat16 g_Ahi[TT*BB_*DD];
__device__ __nv_bfloat16 g_Alo[TT*BB_*DD];
__device__ __nv_bfloat16 g_Whi[7*DD*DD];
__device__ __nv_bfloat16 g_Wlo[7*DD*DD];

// grid-barrier state for persistent GRU scan
__device__ unsigned g_bar_count = 0;
__device__ unsigned g_bar_gen   = 0;

// ---------------- generic helpers --------------------------------------------
__device__ __forceinline__ uint32_t f2tf32(float x) {
    uint32_t r;
    asm("cvt.rna.tf32.f32 %0, %1;" : "=r"(r) : "f"(x));
    return r;
}

__device__ __forceinline__ void cp_async16(uint32_t smem_addr, const void* gmem_ptr) {
    asm volatile("cp.async.cg.shared.global [%0], [%1], 16;" :: "r"(smem_addr), "l"(gmem_ptr));
}

__device__ __forceinline__ unsigned ld_acquire_u32(unsigned* p) {
    unsigned v;
    asm volatile("ld.acquire.gpu.u32 %0, [%1];" : "=r"(v) : "l"(p) : "memory");
    return v;
}

// release/acquire grid barrier; all NBLK blocks must be co-resident
__device__ __forceinline__ void grid_barrier(unsigned nblk) {
    __threadfence();
    __syncthreads();
    if (threadIdx.x == 0) {
        unsigned gen = *((volatile unsigned*)&g_bar_gen);   // read BEFORE arrive
        unsigned arrived = atomicAdd(&g_bar_count, 1u);
        if (arrived == nblk - 1) {
            g_bar_count = 0;
            __threadfence();
            atomicAdd(&g_bar_gen, 1u);
        } else {
            while (ld_acquire_u32(&g_bar_gen) == gen) { __nanosleep(32); }
        }
    }
    __syncthreads();
}

__device__ __forceinline__ uint32_t smem_to_u32(const void* smem_ptr) {
    uint32_t addr;
    asm("{ .reg .u64 tmp; cvta.to.shared.u64 tmp, %1; cvt.u32.u64 %0, tmp; }"
        : "=r"(addr) : "l"(smem_ptr));
    return addr;
}

#define MBAR_INIT(mbar, cnt) \
    asm volatile("mbarrier.init.shared.b64 [%0], %1;" \
        :: "r"((uint32_t)(mbar)), "r"((uint32_t)(cnt)) : "memory")

#define MBAR_WAIT_PARITY(mbar_addr, parity) do { \
    uint32_t _m = (uint32_t)(mbar_addr); \
    uint32_t _p = (uint32_t)(parity); \
    uint32_t _done; \
    asm volatile( \
        "{\n\t.reg .pred p;\n\t" \
        "mbarrier.try_wait.parity.acquire.cta.shared::cta.b64 p, [%1], %2;\n\t" \
        "selp.b32 %0, 1, 0, p;\n\t}" \
        : "=r"(_done) : "r"(_m), "r"(_p) : "memory"); \
    if (!_done) { \
        asm volatile( \
            "{\n\t.reg .pred P1;\n\t" \
            "WAIT_LOOP_%=:\n\t" \
            "mbarrier.try_wait.parity.acquire.cta.shared::cta.b64 P1, [%0], %1, 0x989680;\n\t" \
            "@P1 bra.uni WAIT_DONE_%=;\n\t" \
            "bra.uni WAIT_LOOP_%=;\n\t" \
            "WAIT_DONE_%=:\n\t}" \
            :: "r"(_m), "r"(_p) : "memory"); \
    } \
} while(0)

#if HAS_TCGEN05
// ---------------- tcgen05 helpers (sm_103a pass only) ------------------------
__device__ __forceinline__ uint32_t elect_one_pred() {
    uint32_t pred;
    asm volatile(
        "{\n\t.reg .pred p;\n\telect.sync _|p, 0xFFFFFFFF;\n\tselp.b32 %0, 1, 0, p;\n\t}"
        : "=r"(pred));
    return pred;
}

#define TCG_ALLOC(smem_result_addr, nCols) \
    asm volatile("tcgen05.alloc.cta_group::1.sync.aligned.shared::cta.b32 [%0], %1;" \
        :: "r"((uint32_t)(smem_result_addr)), "r"((uint32_t)(nCols)) : "memory")
#define TCG_DEALLOC(tmem_addr, nCols) \
    asm volatile("tcgen05.dealloc.cta_group::1.sync.aligned.b32 %0, %1;" \
        :: "r"(tmem_addr), "r"((uint32_t)(nCols)))
#define TCG_COMMIT(mbar) \
    asm volatile("tcgen05.commit.cta_group::1.mbarrier::arrive::one.shared::cluster.b64 [%0];" \
        :: "r"((uint32_t)(mbar)) : "memory")
#define TCG_FENCE_BEFORE() asm volatile("tcgen05.fence::before_thread_sync;" ::: "memory")
#define TCG_FENCE_AFTER()  asm volatile("tcgen05.fence::after_thread_sync;" ::: "memory")
#define FENCE_PROXY_ASYNC() asm volatile("fence.proxy.async.shared::cta;" ::: "memory")
#define TCG_WAIT_LD() asm volatile("tcgen05.wait::ld.sync.aligned;" ::: "memory")

#define TCG_LD_32X32B_X32(r, tmem_addr) \
    asm volatile( \
        "tcgen05.ld.sync.aligned.32x32b.x32.b32 " \
        "{%0, %1, %2, %3, %4, %5, %6, %7, " \
        " %8, %9, %10, %11, %12, %13, %14, %15, " \
        " %16, %17, %18, %19, %20, %21, %22, %23, " \
        " %24, %25, %26, %27, %28, %29, %30, %31}, [%32];" \
        : "=r"((r)[0]),  "=r"((r)[1]),  "=r"((r)[2]),  "=r"((r)[3]), \
          "=r"((r)[4]),  "=r"((r)[5]),  "=r"((r)[6]),  "=r"((r)[7]), \
          "=r"((r)[8]),  "=r"((r)[9]),  "=r"((r)[10]), "=r"((r)[11]), \
          "=r"((r)[12]), "=r"((r)[13]), "=r"((r)[14]), "=r"((r)[15]), \
          "=r"((r)[16]), "=r"((r)[17]), "=r"((r)[18]), "=r"((r)[19]), \
          "=r"((r)[20]), "=r"((r)[21]), "=r"((r)[22]), "=r"((r)[23]), \
          "=r"((r)[24]), "=r"((r)[25]), "=r"((r)[26]), "=r"((r)[27]), \
          "=r"((r)[28]), "=r"((r)[29]), "=r"((r)[30]), "=r"((r)[31]) \
        : "r"(tmem_addr))

__device__ __forceinline__ void tcg_mma_f16_ss(
    uint32_t d_tmem, uint64_t a_desc, uint64_t b_desc, uint32_t idesc, bool en)
{
    uint32_t e = en ? 1u : 0u;
    asm volatile(
        "{\n\t.reg .pred p;\n\tsetp.ne.u32 p, %4, 0;\n\t"
        "tcgen05.mma.cta_group::1.kind::f16 [%0], %1, %2, %3, {%5, %5, %5, %5}, p;\n\t}"
        :: "r"(d_tmem), "l"(a_desc), "l"(b_desc), "r"(idesc), "r"(e), "r"(0u)
        : "memory");
}
#endif  // HAS_TCGEN05

// SW128 K-major smem descriptor: layout=2, version=1(Blackwell), SBO=64, LBO=1
static constexpr uint64_t SMEM_DESC_BASE_SW128 =
    (uint64_t(2) << 61) | (uint64_t(1) << 46) | (uint64_t(64) << 32) | (uint64_t(1) << 16);
#define MAKE_DESC(addr) (SMEM_DESC_BASE_SW128 | ((uint64_t)((addr) >> 4) & 0x3FFF))
#define SWZ128(off) ((off) ^ (((off) >> 3) & 0x70))

// idesc kind::f16: dtype F32(1<<4), atype BF16(1<<7), btype BF16(1<<10),
// N=128 -> 16<<17, M=128 -> 8<<24   (formula validated by test_mma.cu)
static constexpr uint32_t IDESC_BF16_128x128 =
    (1u << 4) | (1u << 7) | (1u << 10) | (16u << 17) | (8u << 24);

// ---------------- conversion kernels ------------------------------------------
__global__ __launch_bounds__(256) void convert_act(
    const float* __restrict__ src,
    __nv_bfloat16* __restrict__ hi, __nv_bfloat16* __restrict__ lo, int n4)
{
    int i = blockIdx.x * blockDim.x + threadIdx.x;
    if (i >= n4) return;
    float4 v = ((const float4*)src)[i];
    __nv_bfloat16 h0 = __float2bfloat16(v.x), h1 = __float2bfloat16(v.y),
                  h2 = __float2bfloat16(v.z), h3 = __float2bfloat16(v.w);
    __nv_bfloat16 l0 = __float2bfloat16(v.x - __bfloat162float(h0));
    __nv_bfloat16 l1 = __float2bfloat16(v.y - __bfloat162float(h1));
    __nv_bfloat16 l2 = __float2bfloat16(v.z - __bfloat162float(h2));
    __nv_bfloat16 l3 = __float2bfloat16(v.w - __bfloat162float(h3));
    ((ushort4*)hi)[i] = make_ushort4(__bfloat16_as_ushort(h0), __bfloat16_as_ushort(h1),
                                     __bfloat16_as_ushort(h2), __bfloat16_as_ushort(h3));
    ((ushort4*)lo)[i] = make_ushort4(__bfloat16_as_ushort(l0), __bfloat16_as_ushort(l1),
                                     __bfloat16_as_ushort(l2), __bfloat16_as_ushort(l3));
}

// transpose + split all 7 weight matrices: W[k][n] -> Wt_hi/lo[m][n][k]
__global__ __launch_bounds__(256) void convert_wt(
    const float* __restrict__ Wm, const float* __restrict__ Wi,
    const float* __restrict__ Wo,
    __nv_bfloat16* __restrict__ hi, __nv_bfloat16* __restrict__ lo)
{
    __shared__ float tile[32][33];
    const int m = blockIdx.z;
    const float* src = (m < 3) ? (Wm + (size_t)m * DD * DD)
                    : (m < 6) ? (Wi + (size_t)(m - 3) * DD * DD) : Wo;
    const int k0 = blockIdx.y * 32, n0 = blockIdx.x * 32;
    const int tx = threadIdx.x & 31, ty = threadIdx.x >> 5;   // 32 x 8
    #pragma unroll
    for (int r = 0; r < 32; r += 8)
        tile[ty + r][tx] = src[(size_t)(k0 + ty + r) * DD + n0 + tx];
    __syncthreads();
    #pragma unroll
    for (int r = 0; r < 32; r += 8) {
        float v = tile[tx][ty + r];              // = src[k0+tx][n0+ty+r]
        __nv_bfloat16 h = __float2bfloat16(v);
        __nv_bfloat16 l = __float2bfloat16(v - __bfloat162float(h));
        size_t o = (size_t)m * DD * DD + (size_t)(n0 + ty + r) * DD + k0 + tx;
        hi[o] = h; lo[o] = l;
    }
}

// ---------------- tcgen05 split-bf16 GEMM, cp.async 3-stage -------------------
#define ST_BYTES 65536
#define ST_ALO   16384
#define ST_BHI   32768
#define ST_BLO   49152
#define TC_SMEM  (1024 + 3*ST_BYTES)    // 197632

__global__ __launch_bounds__(256, 1) void gemm_tc(
    const __nv_bfloat16* __restrict__ Ahi, const __nv_bfloat16* __restrict__ Alo,
    const __nv_bfloat16* __restrict__ Bhi, const __nv_bfloat16* __restrict__ Blo,
    float* __restrict__ C, const float* __restrict__ bias)
{
#if HAS_TCGEN05
    extern __shared__ char smem[];
    const uint32_t smem_base = smem_to_u32(smem);
    const int tid = threadIdx.x;
    const int wid = tid >> 5, lane = tid & 31;
    const int bx = blockIdx.x, by = blockIdx.y;    // n tile (0..3), m tile

    if (wid == 0) TCG_ALLOC(smem_base + 0, 128);
    if (tid == 0) {
        MBAR_INIT(smem_base + 8,  1);
        MBAR_INIT(smem_base + 16, 1);
        MBAR_INIT(smem_base + 24, 1);
    }
    __syncthreads();
    uint32_t tmem_base;
    asm volatile("ld.shared.b32 %0, [%1];" : "=r"(tmem_base) : "r"(smem_base + 0));

    const int row = tid >> 1;                  // 0..127
    const int ub  = (tid & 1) * 4;             // 16B unit base (0 or 4)
    const size_t a_goff = ((size_t)(by * 128 + row) * DD) * 2;  // bytes
    const size_t b_goff = ((size_t)(bx * 128 + row) * DD) * 2;  // bytes (B row = n)

    const char* pAhi = (const char*)Ahi + a_goff;
    const char* pAlo = (const char*)Alo + a_goff;
    const char* pBhi = (const char*)Bhi + b_goff;
    const char* pBlo = (const char*)Blo + b_goff;

    auto issue_load = [&](int c, int s) {
        uint32_t st = smem_base + 1024 + s * ST_BYTES;
        int cb = c * 128;
        #pragma unroll
        for (int i = 0; i < 4; i++) {
            int u = ub + i;
            uint32_t dsw = SWZ128((uint32_t)(row * 128 + u * 16));
            int go = cb + u * 16;
            cp_async16(st +           dsw, pAhi + go);
            cp_async16(st + ST_ALO  + dsw, pAlo + go);
            cp_async16(st + ST_BHI  + dsw, pBhi + go);
            cp_async16(st + ST_BLO  + dsw, pBlo + go);
        }
        asm volatile("cp.async.commit_group;");
    };

    issue_load(0, 0);
    issue_load(1, 1);
    issue_load(2, 2);

    int phase[3] = {0, 0, 0};

    #pragma unroll
    for (int c = 0; c < 8; c++) {
        const int s = c - (c >= 6 ? 6 : (c >= 3 ? 3 : 0));   // c % 3
        if (c <= 5)      asm volatile("cp.async.wait_group 2;");
        else if (c == 6) asm volatile("cp.async.wait_group 1;");
        else             asm volatile("cp.async.wait_group 0;");
        __syncthreads();
        FENCE_PROXY_ASYNC();

        if (wid == 0 && elect_one_pred()) {
            uint32_t st = smem_base + 1024 + s * ST_BYTES;
            uint64_t ah = MAKE_DESC(st);
            uint64_t al = MAKE_DESC(st + ST_ALO);
            uint64_t bh = MAKE_DESC(st + ST_BHI);
            uint64_t bl = MAKE_DESC(st + ST_BLO);
            #pragma unroll
            for (int ks = 0; ks < 4; ks++) {
                uint64_t off = (uint64_t)(ks * 2);
                tcg_mma_f16_ss(tmem_base, ah + off, bh + off, IDESC_BF16_128x128,
                               !(c == 0 && ks == 0));
                tcg_mma_f16_ss(tmem_base, ah + off, bl + off, IDESC_BF16_128x128, true);
                tcg_mma_f16_ss(tmem_base, al + off, bh + off, IDESC_BF16_128x128, true);
            }
            TCG_COMMIT(smem_base + 8 + s * 8);
        }

        if (c + 3 < 8) {
            MBAR_WAIT_PARITY(smem_base + 8 + s * 8, phase[s]);
            phase[s] ^= 1;
            issue_load(c + 3, s);
        }
    }

    MBAR_WAIT_PARITY(smem_base + 8,  phase[0]);
    MBAR_WAIT_PARITY(smem_base + 16, phase[1]);
    MBAR_WAIT_PARITY(smem_base + 24, phase[2]);
    TCG_FENCE_AFTER();
    __syncthreads();

    float* ds = (float*)(smem + 1024);
    if (wid < 4) {
        int r0 = wid * 32 + lane;
        #pragma unroll
        for (int r = 0; r < 4; r++) {
            uint32_t regs[32];
            TCG_LD_32X32B_X32(regs, tmem_base + r * 32);
            TCG_WAIT_LD();
            #pragma unroll
            for (int q = 0; q < 32; q++)
                ds[r0 * 132 + r * 32 + q] = __uint_as_float(regs[q]);
        }
        TCG_FENCE_BEFORE();
    }
    __syncthreads();
    {
        int r0 = tid >> 1;
        int cb = (tid & 1) * 64;
        float* crow = C + (size_t)(by * 128 + r0) * DD + bx * 128 + cb;
        #pragma unroll
        for (int i = 0; i < 16; i++) {
            float4 v = *(float4*)(ds + r0 * 132 + cb + i * 4);
            if (bias) {
                float4 b = *(const float4*)(bias + bx * 128 + cb + i * 4);
                v.x += b.x; v.y += b.y; v.z += b.z; v.w += b.w;
            }
            *(float4*)(crow + i * 4) = v;
        }
    }
    __syncthreads();
    if (wid == 0) TCG_DEALLOC(tmem_base, 128);

#else
    // compile-only correctness fallback (sm_103a cubin is selected at runtime)
    const int bx = blockIdx.x, by = blockIdx.y, tid = threadIdx.x;
    int r0 = (tid >> 4) * 8;
    int c0 = (tid & 15) * 8;
    for (int i = 0; i < 8; i++)
        for (int j = 0; j < 8; j++) {
            int m = by * 128 + r0 + i, n = bx * 128 + c0 + j;
            float acc = 0.f;
            for (int k = 0; k < DD; k++) {
                float a = __bfloat162float(Ahi[(size_t)m * DD + k]) +
                          __bfloat162float(Alo[(size_t)m * DD + k]);
                float b = __bfloat162float(Bhi[(size_t)n * DD + k]) +
                          __bfloat162float(Blo[(size_t)n * DD + k]);
                acc += a * b;
            }
            if (bias) acc += bias[n];
            C[(size_t)m * DD + n] = acc;
        }
#endif
}

// ---------------- tiny launch-index shifter ----------------------------------
__global__ void warmup_kernel() { if (threadIdx.x == 0) g_bar_count = 0; }

// ---------------- LayerNorm(+bias)+ReLU, fp32 in -> split bf16 out -----------
__global__ __launch_bounds__(128) void ln_bias_relu_bf16(
    const float* __restrict__ X, const float* __restrict__ bias,
    const float* __restrict__ gamma, const float* __restrict__ beta,
    __nv_bfloat16* __restrict__ hi, __nv_bfloat16* __restrict__ lo)
{
    const int row = blockIdx.x;
    const int tid = threadIdx.x;
    const float* xp = X + (size_t)row * DD + tid * 4;
    float4 v = *(const float4*)xp;
    float4 bb = *(const float4*)(bias + tid * 4);
    v.x += bb.x; v.y += bb.y; v.z += bb.z; v.w += bb.w;

    float s  = v.x + v.y + v.z + v.w;
    float sq = v.x*v.x + v.y*v.y + v.z*v.z + v.w*v.w;
    #pragma unroll
    for (int o = 16; o > 0; o >>= 1) {
        s  += __shfl_down_sync(0xffffffffu, s,  o);
        sq += __shfl_down_sync(0xffffffffu, sq, o);
    }
    __shared__ float ws[4], wq[4];
    if ((tid & 31) == 0) { ws[tid >> 5] = s; wq[tid >> 5] = sq; }
    __syncthreads();
    float st = ws[0] + ws[1] + ws[2] + ws[3];
    float qt = wq[0] + wq[1] + wq[2] + wq[3];
    float mean = st * (1.f / DD);
    float var  = qt * (1.f / DD) - mean * mean;
    float inv  = rsqrtf(var + 1e-6f);

    float4 g = *(const float4*)(gamma + tid * 4);
    float4 b2 = *(const float4*)(beta + tid * 4);
    float o0 = fmaxf((v.x - mean) * inv * g.x + b2.x, 0.f);
    float o1 = fmaxf((v.y - mean) * inv * g.y + b2.y, 0.f);
    float o2 = fmaxf((v.z - mean) * inv * g.z + b2.z, 0.f);
    float o3 = fmaxf((v.w - mean) * inv * g.w + b2.w, 0.f);

    __nv_bfloat16 h0 = __float2bfloat16(o0), h1 = __float2bfloat16(o1),
                  h2 = __float2bfloat16(o2), h3 = __float2bfloat16(o3);
    __nv_bfloat16 l0 = __float2bfloat16(o0 - __bfloat162float(h0));
    __nv_bfloat16 l1 = __float2bfloat16(o1 - __bfloat162float(h1));
    __nv_bfloat16 l2 = __float2bfloat16(o2 - __bfloat162float(h2));
    __nv_bfloat16 l3 = __float2bfloat16(o3 - __bfloat162float(h3));
    ((ushort4*)(hi + (size_t)row * DD))[tid] =
        make_ushort4(__bfloat16_as_ushort(h0), __bfloat16_as_ushort(h1),
                     __bfloat16_as_ushort(h2), __bfloat16_as_ushort(h3));
    ((ushort4*)(lo + (size_t)row * DD))[tid] =
        make_ushort4(__bfloat16_as_ushort(l0), __bfloat16_as_ushort(l1),
                     __bfloat16_as_ushort(l2), __bfloat16_as_ushort(l3));
}

// ---------------- LayerNorm(+bias)+ReLU fp32 in place (head) -----------------
__global__ __launch_bounds__(128) void ln_bias_relu(
    float* __restrict__ X, const float* __restrict__ bias,
    const float* __restrict__ gamma, const float* __restrict__ beta)
{
    const int row = blockIdx.x;
    const int tid = threadIdx.x;
    float* xp = X + (size_t)row * DD + tid * 4;
    float4 v = *(float4*)xp;
    float4 bb = *(const float4*)(bias + tid * 4);
    v.x += bb.x; v.y += bb.y; v.z += bb.z; v.w += bb.w;

    float s  = v.x + v.y + v.z + v.w;
    float sq = v.x*v.x + v.y*v.y + v.z*v.z + v.w*v.w;
    #pragma unroll
    for (int o = 16; o > 0; o >>= 1) {
        s  += __shfl_down_sync(0xffffffffu, s,  o);
        sq += __shfl_down_sync(0xffffffffu, sq, o);
    }
    __shared__ float ws[4], wq[4];
    if ((tid & 31) == 0) { ws[tid >> 5] = s; wq[tid >> 5] = sq; }
    __syncthreads();
    float st = ws[0] + ws[1] + ws[2] + ws[3];
    float qt = wq[0] + wq[1] + wq[2] + wq[3];
    float mean = st * (1.f / DD);
    float var  = qt * (1.f / DD) - mean * mean;
    float inv  = rsqrtf(var + 1e-6f);

    float4 g = *(const float4*)(gamma + tid * 4);
    float4 b2 = *(const float4*)(beta + tid * 4);
    float4 o;
    o.x = fmaxf((v.x - mean) * inv * g.x + b2.x, 0.f);
    o.y = fmaxf((v.y - mean) * inv * g.y + b2.y, 0.f);
    o.z = fmaxf((v.z - mean) * inv * g.z + b2.z, 0.f);
    o.w = fmaxf((v.w - mean) * inv * g.w + b2.w, 0.f);
    *(float4*)xp = o;
}

// ---------------- persistent GRU scan: 128 blocks (batch-quarter x d-slice) --
// Block bi: qb = bi>>5 (batch quarter, 64 rows), nd = bi&31 (16 d-cols/gate).
// Warps: wm = warp&3 -> m-tile (16 rows), wn = warp>>2 -> 8-col half.
// h staged per step in 2 k-chunks of 256 (hs[64][260] tf32).
#define GRU_NBLK 128
#define GRU_SMEM_WORDS (3*512*16 + 64*260)    // Ws 24576 + hs 16640 = 41216 words

__device__ __forceinline__ float sigmoidf_(float x) { return 1.f / (1.f + expf(-x)); }

__global__ __launch_bounds__(256, 1) void gru_scan(
    const float* __restrict__ hidden,
    const float* __restrict__ X,
    const int* __restrict__ dones,
    const float* __restrict__ Wh,
    const float* __restrict__ bhn,
    float* __restrict__ y)
{
    extern __shared__ uint32_t smem_u[];
    uint32_t* Ws = smem_u;                 // [gate][k][16]
    uint32_t* hs = smem_u + 3*512*16;      // [64][260]

    const int bi = blockIdx.x;
    const int qb = bi >> 5;                // batch quarter 0..3
    const int nd = bi & 31;                // d-slice
    const int b0 = qb * 64;
    const int d0 = nd * 16;

    const int tid  = threadIdx.x;
    const int warp = tid >> 5, lane = tid & 31;
    const int wm = warp & 3, wn = warp >> 2;   // 4(m=16 rows) x 2(n=8 cols)
    const int m_base = wm * 16;
    const int n8 = wn * 8;
    const int g  = lane >> 2;
    const int tg = lane & 3;

    // stage weights once: Wh[gate][k][d0..d0+16) -> Ws tf32
    #pragma unroll 4
    for (int i = 0; i < 24; i++) {
        int q = tid + i * 256;
        int gate = q >> 11;
        int rem  = q & 2047;
        int k    = rem >> 2;
        int dl4  = (rem & 3) * 4;
        float4 w = *(const float4*)(Wh + ((size_t)gate * 512 + k) * 512 + d0 + dl4);
        uint4 u = make_uint4(f2tf32(w.x), f2tf32(w.y), f2tf32(w.z), f2tf32(w.w));
        *(uint4*)(&Ws[((gate << 9) + k) * 16 + dl4]) = u;
    }

    const int dcol = d0 + n8 + tg * 2;
    const float bh0 = bhn[dcol], bh1 = bhn[dcol + 1];
    __syncthreads();

    for (int t = 0; t < TT; t++) {
        const float* hprev = (t == 0) ? hidden : (y + (size_t)(t - 1) * BD);
        const int* dn = dones + (size_t)t * BB_;

        // prefetch epilogue operands: rows m_base + j*8 + g, j in {0,1}
        float2 xr2[2], xz2[2], xn2[2], hp2[2];
        #pragma unroll
        for (int j = 0; j < 2; j++) {
            int bglob = b0 + m_base + j * 8 + g;
            int df = dn[bglob];
            size_t gi = (size_t)bglob * DD + dcol;
            hp2[j] = df ? make_float2(0.f, 0.f) : *(const float2*)(hprev + gi);
            size_t xi = (size_t)t * BD + gi;
            xr2[j] = *(const float2*)(X + xi);
            xz2[j] = *(const float2*)(X + TBD + xi);
            xn2[j] = *(const float2*)(X + 2 * TBD + xi);
        }

        float c[3][4];
        #pragma unroll
        for (int gt = 0; gt < 3; gt++)
            #pragma unroll
            for (int q = 0; q < 4; q++) c[gt][q] = 0.f;

        // 2 k-chunks of 256
        #pragma unroll
        for (int kc = 0; kc < 2; kc++) {
            const int kbase = kc * 256;
            // stage h chunk: 64 rows x 256 floats (tf32, done-masked)
            #pragma unroll 4
            for (int i = 0; i < 16; i++) {
                int linear = tid + i * 256;
                int row = linear >> 6;             // 0..63
                int c4  = (linear & 63) * 4;       // 0..252
                int gb  = b0 + row;
                float4 v;
                if (dn[gb]) v = make_float4(0.f, 0.f, 0.f, 0.f);
                else v = *(const float4*)(hprev + (size_t)gb * DD + kbase + c4);
                uint4 u = make_uint4(f2tf32(v.x), f2tf32(v.y), f2tf32(v.z), f2tf32(v.w));
                *(uint4*)(&hs[row * 260 + c4]) = u;
            }
            __syncthreads();

            #pragma unroll 8
            for (int kt = 0; kt < 32; kt++) {
                const int kb = kt * 8;
                uint32_t af[4];
                {
                    int rb = (m_base + g) * 260;
                    af[0] = hs[rb +         kb + tg    ];
                    af[1] = hs[rb + 8*260 + kb + tg    ];
                    af[2] = hs[rb +         kb + tg + 4];
                    af[3] = hs[rb + 8*260 + kb + tg + 4];
                }
                const int kg = kbase + kb;
                #pragma unroll
                for (int gt = 0; gt < 3; gt++) {
                    uint32_t b0r = Ws[((gt << 9) + kg + tg    ) * 16 + n8 + g];
                    uint32_t b1r = Ws[((gt << 9) + kg + tg + 4) * 16 + n8 + g];
                    asm volatile(
                        "mma.sync.aligned.m16n8k8.row.col.f32.tf32.tf32.f32 "
                        "{%0,%1,%2,%3}, {%4,%5,%6,%7}, {%8,%9}, {%0,%1,%2,%3};"
                        : "+f"(c[gt][0]), "+f"(c[gt][1]),
                          "+f"(c[gt][2]), "+f"(c[gt][3])
                        : "r"(af[0]), "r"(af[1]), "r"(af[2]), "r"(af[3]),
                          "r"(b0r), "r"(b1r));
                }
            }
            __syncthreads();
        }

        // elementwise GRU update, write y[t]
        #pragma unroll
        for (int j = 0; j < 2; j++) {
            int q0 = j * 2;
            int bglob = b0 + m_base + j * 8 + g;
            float r0 = sigmoidf_(xr2[j].x + c[0][q0]);
            float r1 = sigmoidf_(xr2[j].y + c[0][q0 + 1]);
            float z0 = sigmoidf_(xz2[j].x + c[1][q0]);
            float z1 = sigmoidf_(xz2[j].y + c[1][q0 + 1]);
            float n0 = tanhf(xn2[j].x + r0 * (c[2][q0]     + bh0));
            float n1 = tanhf(xn2[j].y + r1 * (c[2][q0 + 1] + bh1));
            float2 o;
            o.x = (1.f - z0) * n0 + z0 * hp2[j].x;
            o.y = (1.f - z1) * n1 + z1 * hp2[j].y;
            *(float2*)(y + (size_t)t * BD + (size_t)bglob * DD + dcol) = o;
        }

        grid_barrier(GRU_NBLK);
    }
}

// ---------------- actor head: logits = X@Wa + ba, availability mask ----------
__global__ __launch_bounds__(256) void head_gemm(
    const float* __restrict__ X, const float* __restrict__ Wa,
    const float* __restrict__ ba, const int* __restrict__ avail,
    float* __restrict__ out, int M)
{
    const int r = blockIdx.x * 8 + (threadIdx.x >> 5);
    const int a = threadIdx.x & 31;
    const float* xr = X + (size_t)r * DD;
    float acc = 0.f;
    #pragma unroll 8
    for (int k = 0; k < DD; k += 4) {
        float4 xv = *(const float4*)(xr + k);
        acc += xv.x * __ldg(Wa + (k + 0) * AA + a);
        acc += xv.y * __ldg(Wa + (k + 1) * AA + a);
        acc += xv.z * __ldg(Wa + (k + 2) * AA + a);
        acc += xv.w * __ldg(Wa + (k + 3) * AA + a);
    }
    float av = (float)avail[(size_t)r * AA + a];
    out[(size_t)r * AA + a] = acc + ba[a] - (1.f - av) * 1e10f;
}

__global__ void copy_kernel(const float* __restrict__ src, float* __restrict__ dst, int n)
{
    int i = blockIdx.x * blockDim.x + threadIdx.x;
    if (i < n) dst[i] = src[i];
}

// ---------------- host orchestration ----------------------------------------
extern "C" void kernel_launch(void* const* d_in, const int* in_sizes, int n_in,
                              void* d_out, int out_size)
{
    const float*          hidden = (const float*)d_in[0];
    const float*          obs    = (const float*)d_in[1];
    const int*            dones  = (const int*)d_in[2];   // bool promoted to int32
    const int*            avail  = (const int*)d_in[3];
    const float*          Wm     = (const float*)d_in[4];
    const float*          bm     = (const float*)d_in[5];
    const float*          lns    = (const float*)d_in[6];
    const float*          lnb    = (const float*)d_in[7];
    const float*          Wi     = (const float*)d_in[8];
    const float*          bi     = (const float*)d_in[9];
    const float*          Wh     = (const float*)d_in[10];
    const float*          bhn    = (const float*)d_in[11];
    const float*          Wo     = (const float*)d_in[12];
    const float*          bo     = (const float*)d_in[13];
    const float*          ln2s   = (const float*)d_in[14];
    const float*          ln2b   = (const float*)d_in[15];
    const float*          Wa     = (const float*)d_in[16];
    const float*          ba     = (const float*)d_in[17];
    float* out = (float*)d_out;

    float *bufA, *bufB, *Xbuf, *ybuf;
    __nv_bfloat16 *Ahi, *Alo, *Whi, *Wlo;
    cudaGetSymbolAddress((void**)&bufA, g_bufA);
    cudaGetSymbolAddress((void**)&bufB, g_bufB);
    cudaGetSymbolAddress((void**)&Xbuf, g_X);
    cudaGetSymbolAddress((void**)&ybuf, g_y);
    cudaGetSymbolAddress((void**)&Ahi, g_Ahi);
    cudaGetSymbolAddress((void**)&Alo, g_Alo);
    cudaGetSymbolAddress((void**)&Whi, g_Whi);
    cudaGetSymbolAddress((void**)&Wlo, g_Wlo);

    cudaFuncSetAttribute(gemm_tc, cudaFuncAttributeMaxDynamicSharedMemorySize, TC_SMEM);

    const dim3 ggrid(DD / 128, MM / 128);   // (4, 512)
    const int WSZ = DD * DD;                // 262144

    warmup_kernel<<<1, 32>>>();
    convert_wt<<<dim3(16, 16, 7), 256>>>(Wm, Wi, Wo, Whi, Wlo);
    convert_act<<<(int)(TBD / 4 / 256), 256>>>(obs, Ahi, Alo, (int)(TBD / 4));

    // --- MLP encoder: 3x (GEMM -> LN+split) ---
    for (int l = 0; l < LL; l++) {
        gemm_tc<<<ggrid, 256, TC_SMEM>>>(Ahi, Alo,
                                         Whi + (size_t)l * WSZ, Wlo + (size_t)l * WSZ,
                                         bufA, nullptr);
        ln_bias_relu_bf16<<<MM, 128>>>(bufA, bm + l * DD, lns + l * DD, lnb + l * DD,
                                       Ahi, Alo);
    }

    // --- input-gate activations: X[g] = e @ Wi[g] + bi[g] ---
    for (int g = 0; g < 3; g++) {
        gemm_tc<<<ggrid, 256, TC_SMEM>>>(Ahi, Alo,
                                         Whi + (size_t)(3 + g) * WSZ,
                                         Wlo + (size_t)(3 + g) * WSZ,
                                         Xbuf + (size_t)g * TBD, bi + g * DD);
    }

    // --- persistent GRU scan: all 256 steps in one kernel, 128 blocks ---
    static const int gru_smem = GRU_SMEM_WORDS * 4;   // 164864 bytes
    cudaFuncSetAttribute(gru_scan, cudaFuncAttributeMaxDynamicSharedMemorySize, gru_smem);
    gru_scan<<<GRU_NBLK, 256, gru_smem>>>(hidden, Xbuf, dones, Wh, bhn, ybuf);

    // --- actor head ---
    convert_act<<<(int)(TBD / 4 / 256), 256>>>(ybuf, Ahi, Alo, (int)(TBD / 4));
    gemm_tc<<<ggrid, 256, TC_SMEM>>>(Ahi, Alo,
                                     Whi + (size_t)6 * WSZ, Wlo + (size_t)6 * WSZ,
                                     bufB, nullptr);
    ln_bias_relu<<<MM, 128>>>(bufB, bo, ln2s, ln2b);

    bool has_hidden = (out_size >= (int)(BD + (size_t)MM * AA));
    float* logits_out = out + (has_hidden ? BD : 0);
    head_gemm<<<MM / 8, 256>>>(bufB, Wa, ba, avail, logits_out, MM);

    if (has_hidden) {
        copy_kernel<<<(BD + 255) / 256, 256>>>(ybuf + (size_t)(TT - 1) * BD, out, BD);
    }
}

// round 17
// speedup vs baseline: 1.7519x; 1.0748x over previous
#include <cuda_runtime.h>
#include <cuda_bf16.h>
#include <math.h>
#include <stdint.h>

#define TT 256
#define BB_ 256
#define DD 512
#define AA 32
#define LL 3
#define MM (TT*BB_)            // 65536 rows
#define TBD ((size_t)MM*DD)    // 33554432
#define BD (BB_*DD)            // 131072

// arch-specific feature gate: tcgen05 only exists in the sm_103a ("a") pass
#if defined(__CUDA_ARCH__) && (defined(__CUDA_ARCH_FEAT_SM103_ALL) || \
    (defined(__CUDA_ARCH_SPECIFIC__) && (__CUDA_ARCH_SPECIFIC__ == 1030)))
#define HAS_TCGEN05 1
#else
#define HAS_TCGEN05 0
#endif

// ---------------- scratch (device globals; no runtime allocation) -----------
__device__ float g_bufA[TT*BB_*DD];
__device__ float g_bufB[TT*BB_*DD];
__device__ float g_X[3ull*TT*BB_*DD];
__device__ float g_y[TT*BB_*DD];
__device__ __nv_bfloat16 g_Ahi[TT*BB_*DD];
__device__ __nv_bfloat16 g_Alo[TT*BB_*DD];
__device__ __nv_bfloat16 g_Whi[7*DD*DD];
__device__ __nv_bfloat16 g_Wlo[7*DD*DD];

// per-quarter grid-barrier state for persistent GRU scan
__device__ unsigned g_bar_count4[4] = {0, 0, 0, 0};
__device__ unsigned g_bar_gen4[4]   = {0, 0, 0, 0};
__device__ unsigned g_bar_count = 0;   // kept for warmup_kernel compat

// ---------------- generic helpers --------------------------------------------
__device__ __forceinline__ uint32_t f2tf32(float x) {
    uint32_t r;
    asm("cvt.rna.tf32.f32 %0, %1;" : "=r"(r) : "f"(x));
    return r;
}

__device__ __forceinline__ void cp_async16(uint32_t smem_addr, const void* gmem_ptr) {
    asm volatile("cp.async.cg.shared.global [%0], [%1], 16;" :: "r"(smem_addr), "l"(gmem_ptr));
}

__device__ __forceinline__ unsigned ld_acquire_u32(unsigned* p) {
    unsigned v;
    asm volatile("ld.acquire.gpu.u32 %0, [%1];" : "=r"(v) : "l"(p) : "memory");
    return v;
}

// release/acquire barrier among `nblk` blocks sharing counter/gen slot `q`
__device__ __forceinline__ void quarter_barrier(int q, unsigned nblk) {
    __threadfence();
    __syncthreads();
    if (threadIdx.x == 0) {
        unsigned gen = *((volatile unsigned*)&g_bar_gen4[q]);   // read BEFORE arrive
        unsigned arrived = atomicAdd(&g_bar_count4[q], 1u);
        if (arrived == nblk - 1) {
            g_bar_count4[q] = 0;
            __threadfence();
            atomicAdd(&g_bar_gen4[q], 1u);
        } else {
            while (ld_acquire_u32(&g_bar_gen4[q]) == gen) { __nanosleep(32); }
        }
    }
    __syncthreads();
}

__device__ __forceinline__ uint32_t smem_to_u32(const void* smem_ptr) {
    uint32_t addr;
    asm("{ .reg .u64 tmp; cvta.to.shared.u64 tmp, %1; cvt.u32.u64 %0, tmp; }"
        : "=r"(addr) : "l"(smem_ptr));
    return addr;
}

#define MBAR_INIT(mbar, cnt) \
    asm volatile("mbarrier.init.shared.b64 [%0], %1;" \
        :: "r"((uint32_t)(mbar)), "r"((uint32_t)(cnt)) : "memory")

#define MBAR_WAIT_PARITY(mbar_addr, parity) do { \
    uint32_t _m = (uint32_t)(mbar_addr); \
    uint32_t _p = (uint32_t)(parity); \
    uint32_t _done; \
    asm volatile( \
        "{\n\t.reg .pred p;\n\t" \
        "mbarrier.try_wait.parity.acquire.cta.shared::cta.b64 p, [%1], %2;\n\t" \
        "selp.b32 %0, 1, 0, p;\n\t}" \
        : "=r"(_done) : "r"(_m), "r"(_p) : "memory"); \
    if (!_done) { \
        asm volatile( \
            "{\n\t.reg .pred P1;\n\t" \
            "WAIT_LOOP_%=:\n\t" \
            "mbarrier.try_wait.parity.acquire.cta.shared::cta.b64 P1, [%0], %1, 0x989680;\n\t" \
            "@P1 bra.uni WAIT_DONE_%=;\n\t" \
            "bra.uni WAIT_LOOP_%=;\n\t" \
            "WAIT_DONE_%=:\n\t}" \
            :: "r"(_m), "r"(_p) : "memory"); \
    } \
} while(0)

#if HAS_TCGEN05
// ---------------- tcgen05 helpers (sm_103a pass only) ------------------------
__device__ __forceinline__ uint32_t elect_one_pred() {
    uint32_t pred;
    asm volatile(
        "{\n\t.reg .pred p;\n\telect.sync _|p, 0xFFFFFFFF;\n\tselp.b32 %0, 1, 0, p;\n\t}"
        : "=r"(pred));
    return pred;
}

#define TCG_ALLOC(smem_result_addr, nCols) \
    asm volatile("tcgen05.alloc.cta_group::1.sync.aligned.shared::cta.b32 [%0], %1;" \
        :: "r"((uint32_t)(smem_result_addr)), "r"((uint32_t)(nCols)) : "memory")
#define TCG_DEALLOC(tmem_addr, nCols) \
    asm volatile("tcgen05.dealloc.cta_group::1.sync.aligned.b32 %0, %1;" \
        :: "r"(tmem_addr), "r"((uint32_t)(nCols)))
#define TCG_COMMIT(mbar) \
    asm volatile("tcgen05.commit.cta_group::1.mbarrier::arrive::one.shared::cluster.b64 [%0];" \
        :: "r"((uint32_t)(mbar)) : "memory")
#define TCG_FENCE_BEFORE() asm volatile("tcgen05.fence::before_thread_sync;" ::: "memory")
#define TCG_FENCE_AFTER()  asm volatile("tcgen05.fence::after_thread_sync;" ::: "memory")
#define FENCE_PROXY_ASYNC() asm volatile("fence.proxy.async.shared::cta;" ::: "memory")
#define TCG_WAIT_LD() asm volatile("tcgen05.wait::ld.sync.aligned;" ::: "memory")

#define TCG_LD_32X32B_X32(r, tmem_addr) \
    asm volatile( \
        "tcgen05.ld.sync.aligned.32x32b.x32.b32 " \
        "{%0, %1, %2, %3, %4, %5, %6, %7, " \
        " %8, %9, %10, %11, %12, %13, %14, %15, " \
        " %16, %17, %18, %19, %20, %21, %22, %23, " \
        " %24, %25, %26, %27, %28, %29, %30, %31}, [%32];" \
        : "=r"((r)[0]),  "=r"((r)[1]),  "=r"((r)[2]),  "=r"((r)[3]), \
          "=r"((r)[4]),  "=r"((r)[5]),  "=r"((r)[6]),  "=r"((r)[7]), \
          "=r"((r)[8]),  "=r"((r)[9]),  "=r"((r)[10]), "=r"((r)[11]), \
          "=r"((r)[12]), "=r"((r)[13]), "=r"((r)[14]), "=r"((r)[15]), \
          "=r"((r)[16]), "=r"((r)[17]), "=r"((r)[18]), "=r"((r)[19]), \
          "=r"((r)[20]), "=r"((r)[21]), "=r"((r)[22]), "=r"((r)[23]), \
          "=r"((r)[24]), "=r"((r)[25]), "=r"((r)[26]), "=r"((r)[27]), \
          "=r"((r)[28]), "=r"((r)[29]), "=r"((r)[30]), "=r"((r)[31]) \
        : "r"(tmem_addr))

__device__ __forceinline__ void tcg_mma_f16_ss(
    uint32_t d_tmem, uint64_t a_desc, uint64_t b_desc, uint32_t idesc, bool en)
{
    uint32_t e = en ? 1u : 0u;
    asm volatile(
        "{\n\t.reg .pred p;\n\tsetp.ne.u32 p, %4, 0;\n\t"
        "tcgen05.mma.cta_group::1.kind::f16 [%0], %1, %2, %3, {%5, %5, %5, %5}, p;\n\t}"
        :: "r"(d_tmem), "l"(a_desc), "l"(b_desc), "r"(idesc), "r"(e), "r"(0u)
        : "memory");
}
#endif  // HAS_TCGEN05

// SW128 K-major smem descriptor: layout=2, version=1(Blackwell), SBO=64, LBO=1
static constexpr uint64_t SMEM_DESC_BASE_SW128 =
    (uint64_t(2) << 61) | (uint64_t(1) << 46) | (uint64_t(64) << 32) | (uint64_t(1) << 16);
#define MAKE_DESC(addr) (SMEM_DESC_BASE_SW128 | ((uint64_t)((addr) >> 4) & 0x3FFF))
#define SWZ128(off) ((off) ^ (((off) >> 3) & 0x70))

// idesc kind::f16: dtype F32(1<<4), atype BF16(1<<7), btype BF16(1<<10),
// N=128 -> 16<<17, M=128 -> 8<<24   (formula validated by test_mma.cu)
static constexpr uint32_t IDESC_BF16_128x128 =
    (1u << 4) | (1u << 7) | (1u << 10) | (16u << 17) | (8u << 24);

// ---------------- conversion kernels ------------------------------------------
__global__ __launch_bounds__(256) void convert_act(
    const float* __restrict__ src,
    __nv_bfloat16* __restrict__ hi, __nv_bfloat16* __restrict__ lo, int n4)
{
    int i = blockIdx.x * blockDim.x + threadIdx.x;
    if (i >= n4) return;
    float4 v = ((const float4*)src)[i];
    __nv_bfloat16 h0 = __float2bfloat16(v.x), h1 = __float2bfloat16(v.y),
                  h2 = __float2bfloat16(v.z), h3 = __float2bfloat16(v.w);
    __nv_bfloat16 l0 = __float2bfloat16(v.x - __bfloat162float(h0));
    __nv_bfloat16 l1 = __float2bfloat16(v.y - __bfloat162float(h1));
    __nv_bfloat16 l2 = __float2bfloat16(v.z - __bfloat162float(h2));
    __nv_bfloat16 l3 = __float2bfloat16(v.w - __bfloat162float(h3));
    ((ushort4*)hi)[i] = make_ushort4(__bfloat16_as_ushort(h0), __bfloat16_as_ushort(h1),
                                     __bfloat16_as_ushort(h2), __bfloat16_as_ushort(h3));
    ((ushort4*)lo)[i] = make_ushort4(__bfloat16_as_ushort(l0), __bfloat16_as_ushort(l1),
                                     __bfloat16_as_ushort(l2), __bfloat16_as_ushort(l3));
}

// transpose + split all 7 weight matrices: W[k][n] -> Wt_hi/lo[m][n][k]
__global__ __launch_bounds__(256) void convert_wt(
    const float* __restrict__ Wm, const float* __restrict__ Wi,
    const float* __restrict__ Wo,
    __nv_bfloat16* __restrict__ hi, __nv_bfloat16* __restrict__ lo)
{
    __shared__ float tile[32][33];
    const int m = blockIdx.z;
    const float* src = (m < 3) ? (Wm + (size_t)m * DD * DD)
                    : (m < 6) ? (Wi + (size_t)(m - 3) * DD * DD) : Wo;
    const int k0 = blockIdx.y * 32, n0 = blockIdx.x * 32;
    const int tx = threadIdx.x & 31, ty = threadIdx.x >> 5;   // 32 x 8
    #pragma unroll
    for (int r = 0; r < 32; r += 8)
        tile[ty + r][tx] = src[(size_t)(k0 + ty + r) * DD + n0 + tx];
    __syncthreads();
    #pragma unroll
    for (int r = 0; r < 32; r += 8) {
        float v = tile[tx][ty + r];              // = src[k0+tx][n0+ty+r]
        __nv_bfloat16 h = __float2bfloat16(v);
        __nv_bfloat16 l = __float2bfloat16(v - __bfloat162float(h));
        size_t o = (size_t)m * DD * DD + (size_t)(n0 + ty + r) * DD + k0 + tx;
        hi[o] = h; lo[o] = l;
    }
}

// ---------------- tcgen05 split-bf16 GEMM, cp.async 3-stage -------------------
#define ST_BYTES 65536
#define ST_ALO   16384
#define ST_BHI   32768
#define ST_BLO   49152
#define TC_SMEM  (1024 + 3*ST_BYTES)    // 197632

__global__ __launch_bounds__(256, 1) void gemm_tc(
    const __nv_bfloat16* __restrict__ Ahi, const __nv_bfloat16* __restrict__ Alo,
    const __nv_bfloat16* __restrict__ Bhi, const __nv_bfloat16* __restrict__ Blo,
    float* __restrict__ C, const float* __restrict__ bias)
{
#if HAS_TCGEN05
    extern __shared__ char smem[];
    const uint32_t smem_base = smem_to_u32(smem);
    const int tid = threadIdx.x;
    const int wid = tid >> 5, lane = tid & 31;
    const int bx = blockIdx.x, by = blockIdx.y;    // n tile (0..3), m tile

    if (wid == 0) TCG_ALLOC(smem_base + 0, 128);
    if (tid == 0) {
        MBAR_INIT(smem_base + 8,  1);
        MBAR_INIT(smem_base + 16, 1);
        MBAR_INIT(smem_base + 24, 1);
    }
    __syncthreads();
    uint32_t tmem_base;
    asm volatile("ld.shared.b32 %0, [%1];" : "=r"(tmem_base) : "r"(smem_base + 0));

    const int row = tid >> 1;                  // 0..127
    const int ub  = (tid & 1) * 4;             // 16B unit base (0 or 4)
    const size_t a_goff = ((size_t)(by * 128 + row) * DD) * 2;  // bytes
    const size_t b_goff = ((size_t)(bx * 128 + row) * DD) * 2;  // bytes (B row = n)

    const char* pAhi = (const char*)Ahi + a_goff;
    const char* pAlo = (const char*)Alo + a_goff;
    const char* pBhi = (const char*)Bhi + b_goff;
    const char* pBlo = (const char*)Blo + b_goff;

    auto issue_load = [&](int c, int s) {
        uint32_t st = smem_base + 1024 + s * ST_BYTES;
        int cb = c * 128;
        #pragma unroll
        for (int i = 0; i < 4; i++) {
            int u = ub + i;
            uint32_t dsw = SWZ128((uint32_t)(row * 128 + u * 16));
            int go = cb + u * 16;
            cp_async16(st +           dsw, pAhi + go);
            cp_async16(st + ST_ALO  + dsw, pAlo + go);
            cp_async16(st + ST_BHI  + dsw, pBhi + go);
            cp_async16(st + ST_BLO  + dsw, pBlo + go);
        }
        asm volatile("cp.async.commit_group;");
    };

    issue_load(0, 0);
    issue_load(1, 1);
    issue_load(2, 2);

    int phase[3] = {0, 0, 0};

    #pragma unroll
    for (int c = 0; c < 8; c++) {
        const int s = c - (c >= 6 ? 6 : (c >= 3 ? 3 : 0));   // c % 3
        if (c <= 5)      asm volatile("cp.async.wait_group 2;");
        else if (c == 6) asm volatile("cp.async.wait_group 1;");
        else             asm volatile("cp.async.wait_group 0;");
        __syncthreads();
        FENCE_PROXY_ASYNC();

        if (wid == 0 && elect_one_pred()) {
            uint32_t st = smem_base + 1024 + s * ST_BYTES;
            uint64_t ah = MAKE_DESC(st);
            uint64_t al = MAKE_DESC(st + ST_ALO);
            uint64_t bh = MAKE_DESC(st + ST_BHI);
            uint64_t bl = MAKE_DESC(st + ST_BLO);
            #pragma unroll
            for (int ks = 0; ks < 4; ks++) {
                uint64_t off = (uint64_t)(ks * 2);
                tcg_mma_f16_ss(tmem_base, ah + off, bh + off, IDESC_BF16_128x128,
                               !(c == 0 && ks == 0));
                tcg_mma_f16_ss(tmem_base, ah + off, bl + off, IDESC_BF16_128x128, true);
                tcg_mma_f16_ss(tmem_base, al + off, bh + off, IDESC_BF16_128x128, true);
            }
            TCG_COMMIT(smem_base + 8 + s * 8);
        }

        if (c + 3 < 8) {
            MBAR_WAIT_PARITY(smem_base + 8 + s * 8, phase[s]);
            phase[s] ^= 1;
            issue_load(c + 3, s);
        }
    }

    MBAR_WAIT_PARITY(smem_base + 8,  phase[0]);
    MBAR_WAIT_PARITY(smem_base + 16, phase[1]);
    MBAR_WAIT_PARITY(smem_base + 24, phase[2]);
    TCG_FENCE_AFTER();
    __syncthreads();

    float* ds = (float*)(smem + 1024);
    if (wid < 4) {
        int r0 = wid * 32 + lane;
        #pragma unroll
        for (int r = 0; r < 4; r++) {
            uint32_t regs[32];
            TCG_LD_32X32B_X32(regs, tmem_base + r * 32);
            TCG_WAIT_LD();
            #pragma unroll
            for (int q = 0; q < 32; q++)
                ds[r0 * 132 + r * 32 + q] = __uint_as_float(regs[q]);
        }
        TCG_FENCE_BEFORE();
    }
    __syncthreads();
    {
        int r0 = tid >> 1;
        int cb = (tid & 1) * 64;
        float* crow = C + (size_t)(by * 128 + r0) * DD + bx * 128 + cb;
        #pragma unroll
        for (int i = 0; i < 16; i++) {
            float4 v = *(float4*)(ds + r0 * 132 + cb + i * 4);
            if (bias) {
                float4 b = *(const float4*)(bias + bx * 128 + cb + i * 4);
                v.x += b.x; v.y += b.y; v.z += b.z; v.w += b.w;
            }
            *(float4*)(crow + i * 4) = v;
        }
    }
    __syncthreads();
    if (wid == 0) TCG_DEALLOC(tmem_base, 128);

#else
    // compile-only correctness fallback (sm_103a cubin is selected at runtime)
    const int bx = blockIdx.x, by = blockIdx.y, tid = threadIdx.x;
    int r0 = (tid >> 4) * 8;
    int c0 = (tid & 15) * 8;
    for (int i = 0; i < 8; i++)
        for (int j = 0; j < 8; j++) {
            int m = by * 128 + r0 + i, n = bx * 128 + c0 + j;
            float acc = 0.f;
            for (int k = 0; k < DD; k++) {
                float a = __bfloat162float(Ahi[(size_t)m * DD + k]) +
                          __bfloat162float(Alo[(size_t)m * DD + k]);
                float b = __bfloat162float(Bhi[(size_t)n * DD + k]) +
                          __bfloat162float(Blo[(size_t)n * DD + k]);
                acc += a * b;
            }
            if (bias) acc += bias[n];
            C[(size_t)m * DD + n] = acc;
        }
#endif
}

// ---------------- tiny launch-index shifter ----------------------------------
__global__ void warmup_kernel() { if (threadIdx.x == 0) g_bar_count = 0; }

// ---------------- LayerNorm(+bias)+ReLU, fp32 in -> split bf16 out -----------
__global__ __launch_bounds__(128) void ln_bias_relu_bf16(
    const float* __restrict__ X, const float* __restrict__ bias,
    const float* __restrict__ gamma, const float* __restrict__ beta,
    __nv_bfloat16* __restrict__ hi, __nv_bfloat16* __restrict__ lo)
{
    const int row = blockIdx.x;
    const int tid = threadIdx.x;
    const float* xp = X + (size_t)row * DD + tid * 4;
    float4 v = *(const float4*)xp;
    float4 bb = *(const float4*)(bias + tid * 4);
    v.x += bb.x; v.y += bb.y; v.z += bb.z; v.w += bb.w;

    float s  = v.x + v.y + v.z + v.w;
    float sq = v.x*v.x + v.y*v.y + v.z*v.z + v.w*v.w;
    #pragma unroll
    for (int o = 16; o > 0; o >>= 1) {
        s  += __shfl_down_sync(0xffffffffu, s,  o);
        sq += __shfl_down_sync(0xffffffffu, sq, o);
    }
    __shared__ float ws[4], wq[4];
    if ((tid & 31) == 0) { ws[tid >> 5] = s; wq[tid >> 5] = sq; }
    __syncthreads();
    float st = ws[0] + ws[1] + ws[2] + ws[3];
    float qt = wq[0] + wq[1] + wq[2] + wq[3];
    float mean = st * (1.f / DD);
    float var  = qt * (1.f / DD) - mean * mean;
    float inv  = rsqrtf(var + 1e-6f);

    float4 g = *(const float4*)(gamma + tid * 4);
    float4 b2 = *(const float4*)(beta + tid * 4);
    float o0 = fmaxf((v.x - mean) * inv * g.x + b2.x, 0.f);
    float o1 = fmaxf((v.y - mean) * inv * g.y + b2.y, 0.f);
    float o2 = fmaxf((v.z - mean) * inv * g.z + b2.z, 0.f);
    float o3 = fmaxf((v.w - mean) * inv * g.w + b2.w, 0.f);

    __nv_bfloat16 h0 = __float2bfloat16(o0), h1 = __float2bfloat16(o1),
                  h2 = __float2bfloat16(o2), h3 = __float2bfloat16(o3);
    __nv_bfloat16 l0 = __float2bfloat16(o0 - __bfloat162float(h0));
    __nv_bfloat16 l1 = __float2bfloat16(o1 - __bfloat162float(h1));
    __nv_bfloat16 l2 = __float2bfloat16(o2 - __bfloat162float(h2));
    __nv_bfloat16 l3 = __float2bfloat16(o3 - __bfloat162float(h3));
    ((ushort4*)(hi + (size_t)row * DD))[tid] =
        make_ushort4(__bfloat16_as_ushort(h0), __bfloat16_as_ushort(h1),
                     __bfloat16_as_ushort(h2), __bfloat16_as_ushort(h3));
    ((ushort4*)(lo + (size_t)row * DD))[tid] =
        make_ushort4(__bfloat16_as_ushort(l0), __bfloat16_as_ushort(l1),
                     __bfloat16_as_ushort(l2), __bfloat16_as_ushort(l3));
}

// ---------------- LayerNorm(+bias)+ReLU fp32 in place (head) -----------------
__global__ __launch_bounds__(128) void ln_bias_relu(
    float* __restrict__ X, const float* __restrict__ bias,
    const float* __restrict__ gamma, const float* __restrict__ beta)
{
    const int row = blockIdx.x;
    const int tid = threadIdx.x;
    float* xp = X + (size_t)row * DD + tid * 4;
    float4 v = *(float4*)xp;
    float4 bb = *(const float4*)(bias + tid * 4);
    v.x += bb.x; v.y += bb.y; v.z += bb.z; v.w += bb.w;

    float s  = v.x + v.y + v.z + v.w;
    float sq = v.x*v.x + v.y*v.y + v.z*v.z + v.w*v.w;
    #pragma unroll
    for (int o = 16; o > 0; o >>= 1) {
        s  += __shfl_down_sync(0xffffffffu, s,  o);
        sq += __shfl_down_sync(0xffffffffu, sq, o);
    }
    __shared__ float ws[4], wq[4];
    if ((tid & 31) == 0) { ws[tid >> 5] = s; wq[tid >> 5] = sq; }
    __syncthreads();
    float st = ws[0] + ws[1] + ws[2] + ws[3];
    float qt = wq[0] + wq[1] + wq[2] + wq[3];
    float mean = st * (1.f / DD);
    float var  = qt * (1.f / DD) - mean * mean;
    float inv  = rsqrtf(var + 1e-6f);

    float4 g = *(const float4*)(gamma + tid * 4);
    float4 b2 = *(const float4*)(beta + tid * 4);
    float4 o;
    o.x = fmaxf((v.x - mean) * inv * g.x + b2.x, 0.f);
    o.y = fmaxf((v.y - mean) * inv * g.y + b2.y, 0.f);
    o.z = fmaxf((v.z - mean) * inv * g.z + b2.z, 0.f);
    o.w = fmaxf((v.w - mean) * inv * g.w + b2.w, 0.f);
    *(float4*)xp = o;
}

// ---------------- persistent GRU scan: 128 blocks, pipelined staging ---------
// Block bi: qb = bi>>5 (batch quarter, 64 rows), nd = bi&31 (16 d-cols/gate).
// 4 k-chunks of 128, hs double-buffered; LDG of chunk kc+1 overlaps mma of kc.
// Per-quarter barrier (32 blocks) instead of global.
#define GRU_NBLK 128
#define GRU_QBLK 32
#define GRU_SMEM_WORDS (3*512*16 + 2*64*132)   // Ws 24576 + 2*8448 = 41472 words

__device__ __forceinline__ float sigmoidf_(float x) { return 1.f / (1.f + expf(-x)); }

__global__ __launch_bounds__(256, 1) void gru_scan(
    const float* __restrict__ hidden,
    const float* __restrict__ X,
    const int* __restrict__ dones,
    const float* __restrict__ Wh,
    const float* __restrict__ bhn,
    float* __restrict__ y)
{
    extern __shared__ uint32_t smem_u[];
    uint32_t* Ws = smem_u;                      // [gate][k][16]
    uint32_t* hsb[2] = { smem_u + 3*512*16,     // [64][132] x 2
                         smem_u + 3*512*16 + 64*132 };

    const int bi = blockIdx.x;
    const int qb = bi >> 5;                // batch quarter 0..3
    const int nd = bi & 31;                // d-slice
    const int b0 = qb * 64;
    const int d0 = nd * 16;

    const int tid  = threadIdx.x;
    const int warp = tid >> 5, lane = tid & 31;
    const int wm = warp & 3, wn = warp >> 2;   // 4(m=16 rows) x 2(n=8 cols)
    const int m_base = wm * 16;
    const int n8 = wn * 8;
    const int g  = lane >> 2;
    const int tg = lane & 3;

    // stage weights once: Wh[gate][k][d0..d0+16) -> Ws tf32
    #pragma unroll 4
    for (int i = 0; i < 24; i++) {
        int q = tid + i * 256;
        int gate = q >> 11;
        int rem  = q & 2047;
        int k    = rem >> 2;
        int dl4  = (rem & 3) * 4;
        float4 w = *(const float4*)(Wh + ((size_t)gate * 512 + k) * 512 + d0 + dl4);
        uint4 u = make_uint4(f2tf32(w.x), f2tf32(w.y), f2tf32(w.z), f2tf32(w.w));
        *(uint4*)(&Ws[((gate << 9) + k) * 16 + dl4]) = u;
    }

    // staging coords: chunk = 64 rows x 128 floats = 2048 float4; 8 per thread
    const int srow = tid >> 5;             // base row 0..7 (8 rows per i-step? no:)
    // linear mapping: linear = tid + i*256; row = linear>>5 (0..63), c4 = (linear&31)*4
    const int dcol = d0 + n8 + tg * 2;
    const float bh0 = bhn[dcol], bh1 = bhn[dcol + 1];
    (void)srow;
    __syncthreads();

    for (int t = 0; t < TT; t++) {
        const float* hprev = (t == 0) ? hidden : (y + (size_t)(t - 1) * BD);
        const int* dn = dones + (size_t)t * BB_;

        // prefetch epilogue operands: rows m_base + j*8 + g, j in {0,1}
        float2 xr2[2], xz2[2], xn2[2], hp2[2];
        #pragma unroll
        for (int j = 0; j < 2; j++) {
            int bglob = b0 + m_base + j * 8 + g;
            int df = dn[bglob];
            size_t gi = (size_t)bglob * DD + dcol;
            hp2[j] = df ? make_float2(0.f, 0.f) : *(const float2*)(hprev + gi);
            size_t xi = (size_t)t * BD + gi;
            xr2[j] = *(const float2*)(X + xi);
            xz2[j] = *(const float2*)(X + TBD + xi);
            xn2[j] = *(const float2*)(X + 2 * TBD + xi);
        }

        float c[3][4];
        #pragma unroll
        for (int gt = 0; gt < 3; gt++)
            #pragma unroll
            for (int q = 0; q < 4; q++) c[gt][q] = 0.f;

        // register prefetch of one chunk (8 float4/thread, done-masked)
        float4 pre[8];
        auto load_chunk = [&](int kc) {
            const int kbase = kc * 128;
            #pragma unroll
            for (int i = 0; i < 8; i++) {
                int linear = tid + i * 256;
                int row = linear >> 5;             // 0..63
                int c4  = (linear & 31) * 4;       // 0..124
                int gb  = b0 + row;
                if (dn[gb]) pre[i] = make_float4(0.f, 0.f, 0.f, 0.f);
                else pre[i] = *(const float4*)(hprev + (size_t)gb * DD + kbase + c4);
            }
        };
        auto store_chunk = [&](uint32_t* hs) {
            #pragma unroll
            for (int i = 0; i < 8; i++) {
                int linear = tid + i * 256;
                int row = linear >> 5;
                int c4  = (linear & 31) * 4;
                uint4 u = make_uint4(f2tf32(pre[i].x), f2tf32(pre[i].y),
                                     f2tf32(pre[i].z), f2tf32(pre[i].w));
                *(uint4*)(&hs[row * 132 + c4]) = u;
            }
        };

        load_chunk(0);
        store_chunk(hsb[0]);
        __syncthreads();

        #pragma unroll
        for (int kc = 0; kc < 4; kc++) {
            const uint32_t* hs = hsb[kc & 1];
            if (kc < 3) load_chunk(kc + 1);    // LDG in flight under the mma below

            const int kbase = kc * 128;
            #pragma unroll 4
            for (int kt = 0; kt < 16; kt++) {
                const int kb = kt * 8;
                uint32_t af[4];
                {
                    int rb = (m_base + g) * 132;
                    af[0] = hs[rb +         kb + tg    ];
                    af[1] = hs[rb + 8*132 + kb + tg    ];
                    af[2] = hs[rb +         kb + tg + 4];
                    af[3] = hs[rb + 8*132 + kb + tg + 4];
                }
                const int kg = kbase + kb;
                #pragma unroll
                for (int gt = 0; gt < 3; gt++) {
                    uint32_t b0r = Ws[((gt << 9) + kg + tg    ) * 16 + n8 + g];
                    uint32_t b1r = Ws[((gt << 9) + kg + tg + 4) * 16 + n8 + g];
                    asm volatile(
                        "mma.sync.aligned.m16n8k8.row.col.f32.tf32.tf32.f32 "
                        "{%0,%1,%2,%3}, {%4,%5,%6,%7}, {%8,%9}, {%0,%1,%2,%3};"
                        : "+f"(c[gt][0]), "+f"(c[gt][1]),
                          "+f"(c[gt][2]), "+f"(c[gt][3])
                        : "r"(af[0]), "r"(af[1]), "r"(af[2]), "r"(af[3]),
                          "r"(b0r), "r"(b1r));
                }
            }

            if (kc < 3) store_chunk(hsb[(kc + 1) & 1]);
            __syncthreads();   // hs[(kc+1)&1] ready; all reads of hs[kc&1] done
        }

        // elementwise GRU update, write y[t]
        #pragma unroll
        for (int j = 0; j < 2; j++) {
            int q0 = j * 2;
            int bglob = b0 + m_base + j * 8 + g;
            float r0 = sigmoidf_(xr2[j].x + c[0][q0]);
            float r1 = sigmoidf_(xr2[j].y + c[0][q0 + 1]);
            float z0 = sigmoidf_(xz2[j].x + c[1][q0]);
            float z1 = sigmoidf_(xz2[j].y + c[1][q0 + 1]);
            float n0 = tanhf(xn2[j].x + r0 * (c[2][q0]     + bh0));
            float n1 = tanhf(xn2[j].y + r1 * (c[2][q0 + 1] + bh1));
            float2 o;
            o.x = (1.f - z0) * n0 + z0 * hp2[j].x;
            o.y = (1.f - z1) * n1 + z1 * hp2[j].y;
            *(float2*)(y + (size_t)t * BD + (size_t)bglob * DD + dcol) = o;
        }

        quarter_barrier(qb, GRU_QBLK);
    }
}

// ---------------- actor head: logits = X@Wa + ba, availability mask ----------
__global__ __launch_bounds__(256) void head_gemm(
    const float* __restrict__ X, const float* __restrict__ Wa,
    const float* __restrict__ ba, const int* __restrict__ avail,
    float* __restrict__ out, int M)
{
    const int r = blockIdx.x * 8 + (threadIdx.x >> 5);
    const int a = threadIdx.x & 31;
    const float* xr = X + (size_t)r * DD;
    float acc = 0.f;
    #pragma unroll 8
    for (int k = 0; k < DD; k += 4) {
        float4 xv = *(const float4*)(xr + k);
        acc += xv.x * __ldg(Wa + (k + 0) * AA + a);
        acc += xv.y * __ldg(Wa + (k + 1) * AA + a);
        acc += xv.z * __ldg(Wa + (k + 2) * AA + a);
        acc += xv.w * __ldg(Wa + (k + 3) * AA + a);
    }
    float av = (float)avail[(size_t)r * AA + a];
    out[(size_t)r * AA + a] = acc + ba[a] - (1.f - av) * 1e10f;
}

__global__ void copy_kernel(const float* __restrict__ src, float* __restrict__ dst, int n)
{
    int i = blockIdx.x * blockDim.x + threadIdx.x;
    if (i < n) dst[i] = src[i];
}

// ---------------- host orchestration ----------------------------------------
extern "C" void kernel_launch(void* const* d_in, const int* in_sizes, int n_in,
                              void* d_out, int out_size)
{
    const float*          hidden = (const float*)d_in[0];
    const float*          obs    = (const float*)d_in[1];
    const int*            dones  = (const int*)d_in[2];   // bool promoted to int32
    const int*            avail  = (const int*)d_in[3];
    const float*          Wm     = (const float*)d_in[4];
    const float*          bm     = (const float*)d_in[5];
    const float*          lns    = (const float*)d_in[6];
    const float*          lnb    = (const float*)d_in[7];
    const float*          Wi     = (const float*)d_in[8];
    const float*          bi     = (const float*)d_in[9];
    const float*          Wh     = (const float*)d_in[10];
    const float*          bhn    = (const float*)d_in[11];
    const float*          Wo     = (const float*)d_in[12];
    const float*          bo     = (const float*)d_in[13];
    const float*          ln2s   = (const float*)d_in[14];
    const float*          ln2b   = (const float*)d_in[15];
    const float*          Wa     = (const float*)d_in[16];
    const float*          ba     = (const float*)d_in[17];
    float* out = (float*)d_out;

    float *bufA, *bufB, *Xbuf, *ybuf;
    __nv_bfloat16 *Ahi, *Alo, *Whi, *Wlo;
    cudaGetSymbolAddress((void**)&bufA, g_bufA);
    cudaGetSymbolAddress((void**)&bufB, g_bufB);
    cudaGetSymbolAddress((void**)&Xbuf, g_X);
    cudaGetSymbolAddress((void**)&ybuf, g_y);
    cudaGetSymbolAddress((void**)&Ahi, g_Ahi);
    cudaGetSymbolAddress((void**)&Alo, g_Alo);
    cudaGetSymbolAddress((void**)&Whi, g_Whi);
    cudaGetSymbolAddress((void**)&Wlo, g_Wlo);

    cudaFuncSetAttribute(gemm_tc, cudaFuncAttributeMaxDynamicSharedMemorySize, TC_SMEM);

    const dim3 ggrid(DD / 128, MM / 128);   // (4, 512)
    const int WSZ = DD * DD;                // 262144

    warmup_kernel<<<1, 32>>>();
    convert_wt<<<dim3(16, 16, 7), 256>>>(Wm, Wi, Wo, Whi, Wlo);
    convert_act<<<(int)(TBD / 4 / 256), 256>>>(obs, Ahi, Alo, (int)(TBD / 4));

    // --- MLP encoder: 3x (GEMM -> LN+split) ---
    for (int l = 0; l < LL; l++) {
        gemm_tc<<<ggrid, 256, TC_SMEM>>>(Ahi, Alo,
                                         Whi + (size_t)l * WSZ, Wlo + (size_t)l * WSZ,
                                         bufA, nullptr);
        ln_bias_relu_bf16<<<MM, 128>>>(bufA, bm + l * DD, lns + l * DD, lnb + l * DD,
                                       Ahi, Alo);
    }

    // --- input-gate activations: X[g] = e @ Wi[g] + bi[g] ---
    for (int g = 0; g < 3; g++) {
        gemm_tc<<<ggrid, 256, TC_SMEM>>>(Ahi, Alo,
                                         Whi + (size_t)(3 + g) * WSZ,
                                         Wlo + (size_t)(3 + g) * WSZ,
                                         Xbuf + (size_t)g * TBD, bi + g * DD);
    }

    // --- persistent GRU scan: all 256 steps in one kernel, 128 blocks ---
    static const int gru_smem = GRU_SMEM_WORDS * 4;   // 165888 bytes
    cudaFuncSetAttribute(gru_scan, cudaFuncAttributeMaxDynamicSharedMemorySize, gru_smem);
    gru_scan<<<GRU_NBLK, 256, gru_smem>>>(hidden, Xbuf, dones, Wh, bhn, ybuf);

    // --- actor head ---
    convert_act<<<(int)(TBD / 4 / 256), 256>>>(ybuf, Ahi, Alo, (int)(TBD / 4));
    gemm_tc<<<ggrid, 256, TC_SMEM>>>(Ahi, Alo,
                                     Whi + (size_t)6 * WSZ, Wlo + (size_t)6 * WSZ,
                                     bufB, nullptr);
    ln_bias_relu<<<MM, 128>>>(bufB, bo, ln2s, ln2b);

    bool has_hidden = (out_size >= (int)(BD + (size_t)MM * AA));
    float* logits_out = out + (has_hidden ? BD : 0);
    head_gemm<<<MM / 8, 256>>>(bufB, Wa, ba, avail, logits_out, MM);

    if (has_hidden) {
        copy_kernel<<<(BD + 255) / 256, 256>>>(ybuf + (size_t)(TT - 1) * BD, out, BD);
    }
}